// round 6
// baseline (speedup 1.0000x reference)
#include <cuda_runtime.h>
#include <cuda_bf16.h>
#include <math.h>
#include <float.h>
#include <stdint.h>

#define CH    64
#define IMG_W 256
#define IMG_H 256
#define HWN   65536
#define NB    8
#define PADW  258

// ---------------- device-global scratch -------------------------------------
__device__ __align__(16) __nv_bfloat16 g_padx[NB * PADW * PADW * 128];
__device__ __align__(16) __nv_bfloat16 g_pad1[NB * PADW * PADW * 128];
__device__ __align__(16) __nv_bfloat16 g_rcl [NB * HWN * 128];
__device__ __align__(16) float g_avg[NB * HWN];
__device__ __align__(16) float g_max[NB * HWN];
__device__ __align__(16) float g_sg [NB * HWN];
__device__ float g_chansum[NB * CH];
__device__ __align__(16) __nv_bfloat16 g_Kpk[NB * 2 * 64 * 128];
__device__ __align__(16) uint32_t g_Wfrag[2 * 9 * 2 * 32 * 64];   // B frags, per-thread order
__device__ __align__(16) uint32_t g_Kfrag[NB * 2 * 2 * 32 * 64];  // K frags, per-thread order

// ---------------- helpers ----------------------------------------------------
__device__ __forceinline__ int reflect(int v, int n) {
    if (v < 0) v = -v;
    if (v >= n) v = 2 * n - 2 - v;
    return v;
}
__device__ __forceinline__ uint32_t s2u(const void* p) {
    return (uint32_t)__cvta_generic_to_shared(p);
}
__device__ __forceinline__ uint32_t pack2bf(float a, float b) {
    return ((uint32_t)__bfloat16_as_ushort(__float2bfloat16(a))) |
           ((uint32_t)__bfloat16_as_ushort(__float2bfloat16(b)) << 16);
}
__device__ __forceinline__ void ldsm_x4(uint32_t addr, uint32_t& r0, uint32_t& r1,
                                        uint32_t& r2, uint32_t& r3) {
    asm volatile("ldmatrix.sync.aligned.m8n8.x4.shared.b16 {%0,%1,%2,%3}, [%4];"
                 : "=r"(r0), "=r"(r1), "=r"(r2), "=r"(r3) : "r"(addr));
}
__device__ __forceinline__ void mma16816(float* c, const uint32_t* a,
                                         uint32_t b0, uint32_t b1) {
    asm volatile("mma.sync.aligned.m16n8k16.row.col.f32.bf16.bf16.f32 "
                 "{%0,%1,%2,%3}, {%4,%5,%6,%7}, {%8,%9}, {%0,%1,%2,%3};"
                 : "+f"(c[0]), "+f"(c[1]), "+f"(c[2]), "+f"(c[3])
                 : "r"(a[0]), "r"(a[1]), "r"(a[2]), "r"(a[3]), "r"(b0), "r"(b1));
}
__device__ __forceinline__ void cp16(uint32_t dst, const void* src) {
    asm volatile("cp.async.ca.shared.global [%0], [%1], 16;" :: "r"(dst), "l"(src));
}
#define CP_COMMIT() asm volatile("cp.async.commit_group;" ::: "memory")
#define CP_WAIT0()  asm volatile("cp.async.wait_group 0;" ::: "memory")

// ---------------- init ----------------
__global__ void init_kernel() {
    int i = blockIdx.x * blockDim.x + threadIdx.x;
    if (i < NB * CH) g_chansum[i] = 0.0f;
}

// ---------------- weight frag prepack ---------------------------------------
// g_Wfrag[cv][t9][wn2][lane32][ks8][nt4][rr2] (uint32 = 2 bf16 along k)
__global__ __launch_bounds__(256)
void wfrag_kernel(const float* __restrict__ w1, const float* __restrict__ w2) {
    int idx = blockIdx.x * 256 + threadIdx.x;
    if (idx >= 73728) return;
    int tmp = idx;
    int rr   = tmp & 1;  tmp >>= 1;
    int nt   = tmp & 3;  tmp >>= 2;
    int ks   = tmp & 7;  tmp >>= 3;
    int lane = tmp & 31; tmp >>= 5;
    int wn   = tmp & 1;  tmp >>= 1;
    int t    = tmp % 9;
    int cv   = tmp / 9;
    int n  = wn * 32 + nt * 8 + (lane >> 2);
    int k0 = ks * 16 + rr * 8 + (lane & 3) * 2;
    const float* w = cv ? w2 : w1;
    uint32_t out = 0;
#pragma unroll
    for (int e = 0; e < 2; e++) {
        int k = k0 + e;
        int ch = k & 63;
        float v = w[n * 576 + ch * 9 + t];
        float f = (k < 64) ? v : (v - __bfloat162float(__float2bfloat16(v)));
        out |= ((uint32_t)__bfloat16_as_ushort(__float2bfloat16(f))) << (16 * e);
    }
    g_Wfrag[idx] = out;
}

// ---------------- K frag prepack (after small_kernel) ------------------------
// g_Kfrag[b][set2][wn2][lane32][ks8][nt4][rr2]
__global__ __launch_bounds__(256)
void kfrag_kernel() {
    int idx = blockIdx.x * 256 + threadIdx.x;   // < 65536
    int tmp = idx;
    int rr   = tmp & 1;  tmp >>= 1;
    int nt   = tmp & 3;  tmp >>= 2;
    int ks   = tmp & 7;  tmp >>= 3;
    int lane = tmp & 31; tmp >>= 5;
    int wn   = tmp & 1;  tmp >>= 1;
    int set  = tmp & 1;  tmp >>= 1;
    int b    = tmp;
    int n  = wn * 32 + nt * 8 + (lane >> 2);
    int k0 = ks * 16 + rr * 8 + (lane & 3) * 2;
    const __nv_bfloat16* src = g_Kpk + (size_t)b * 16384 + (set * 64 + n) * 128;
    uint32_t out = ((uint32_t)__bfloat16_as_ushort(src[k0])) |
                   ((uint32_t)__bfloat16_as_ushort(src[k0 + 1]) << 16);
    g_Kfrag[idx] = out;
}

// ---------------- input prepass: fp32 NCHW -> padded ch-last bf16 hi/lo ------
__global__ __launch_bounds__(256)
void pad_input_kernel(const float* __restrict__ x) {
    const int y = blockIdx.x, b = blockIdx.y, px = threadIdx.x;
    float v[64];
#pragma unroll
    for (int c = 0; c < 64; c++)
        v[c] = x[(((size_t)(b * 64 + c)) << 16) + y * 256 + px];
    uint4* dst = (uint4*)(g_padx + (((size_t)b * PADW + y + 1) * PADW + px + 1) * 128);
#pragma unroll
    for (int j = 0; j < 16; j++) {
        int k0 = (j & 7) * 8;
        bool lo = j >= 8;
        uint4 u; uint32_t* wp = (uint32_t*)&u;
#pragma unroll
        for (int q = 0; q < 4; q++) {
            float f0 = v[k0 + 2 * q], f1 = v[k0 + 2 * q + 1];
            if (lo) {
                f0 -= __bfloat162float(__float2bfloat16(f0));
                f1 -= __bfloat162float(__float2bfloat16(f1));
            }
            wp[q] = pack2bf(f0, f1);
        }
        dst[j] = u;
    }
}

// ---------------- border fill (reflect) --------------------------------------
__global__ __launch_bounds__(256)
void border_kernel(__nv_bfloat16* __restrict__ pad) {
    const int b = blockIdx.x;
    uint4* base = (uint4*)(pad + (size_t)b * PADW * PADW * 128);
    const int tid = threadIdx.x;
    for (int i = tid; i < 256 * 2 * 16; i += 256) {
        int j = i & 15, which = (i >> 4) & 1, py = 1 + (i >> 5);
        int sp = which ? 255 : 2, dp = which ? 257 : 0;
        base[((size_t)py * PADW + dp) * 16 + j] = base[((size_t)py * PADW + sp) * 16 + j];
    }
    __syncthreads();
    for (int i = tid; i < 258 * 2 * 16; i += 256) {
        int j = i & 15, which = (i >> 4) & 1, px = (i >> 5);
        int sp = which ? 255 : 2, dp = which ? 257 : 0;
        base[((size_t)dp * PADW + px) * 16 + j] = base[((size_t)sp * PADW + px) * 16 + j];
    }
}

// ---------------- conv: mma.sync, frag-LDG weights, cp.async strips ----------
#define STRIP_B 33280                 // 130 rows x 256B
#define CONV_SMEM (2 * STRIP_B)       // 66560

template <bool IS_CONV2>
__global__ __launch_bounds__(256)
void conv_frag_kernel(const __nv_bfloat16* __restrict__ pad,
                      const uint32_t* __restrict__ wfrag,
                      const float* __restrict__ bias,
                      const float* __restrict__ prelu_a,
                      __nv_bfloat16* __restrict__ outp)
{
    extern __shared__ char smem[];
    float* st = (float*)smem;                     // epilogue reuse: 128 x 68 floats
    __shared__ float s_b[64], s_a[64];

    const int tid = threadIdx.x, lane = tid & 31, wid = tid >> 5;
    const int wm = wid & 3, wn = wid >> 2;
    const int x0 = blockIdx.x * 128, y0 = blockIdx.y, b = blockIdx.z;
    const uint32_t strip_u = s2u(smem);

    if (tid < 64) { s_b[tid] = bias[tid]; s_a[tid] = IS_CONV2 ? 0.f : prelu_a[tid]; }

    float acc[2][4][4];
#pragma unroll
    for (int f = 0; f < 2; f++)
#pragma unroll
        for (int g = 0; g < 4; g++)
#pragma unroll
            for (int c = 0; c < 4; c++) acc[f][g][c] = 0.0f;

    // stage one image-row strip (130 px x 128 bf16) with 16B swizzle
    auto stage = [&](int ky, int buf) {
        const char* src = (const char*)(pad +
            (((size_t)b * PADW + (y0 + ky)) * PADW + x0) * 128);
        const uint32_t du = strip_u + buf * STRIP_B;
        for (int i = tid; i < 2080; i += 256) {
            int p = i >> 4, j = i & 15;
            cp16(du + p * 256 + ((j ^ (p & 7)) << 4), src + i * 16);
        }
    };

    stage(0, 0); CP_COMMIT();
    CP_WAIT0(); __syncthreads();

    int buf = 0;
    for (int ky = 0; ky < 3; ky++) {
        if (ky < 2) { stage(ky + 1, buf ^ 1); CP_COMMIT(); }
        const uint32_t su = strip_u + buf * STRIP_B;
#pragma unroll
        for (int kx = 0; kx < 3; kx++) {
            const int t = ky * 3 + kx;
            const uint32_t* tb = wfrag + ((size_t)(t * 2 + wn) * 32 + lane) * 64;
#pragma unroll
            for (int s = 0; s < 4; s++) {
                uint32_t ah[2][4], al[2][4];
#pragma unroll
                for (int f = 0; f < 2; f++) {
                    int row = kx + wm * 32 + f * 16 + (lane & 15);
                    uint32_t chi = (uint32_t)(s * 2 + (lane >> 4));
                    uint32_t base = su + row * 256;
                    ldsm_x4(base + (((chi    ) ^ (row & 7)) << 4),
                            ah[f][0], ah[f][1], ah[f][2], ah[f][3]);
                    ldsm_x4(base + (((chi + 8) ^ (row & 7)) << 4),
                            al[f][0], al[f][1], al[f][2], al[f][3]);
                }
                uint4 h0 = *(const uint4*)(tb + s * 8);
                uint4 h1 = *(const uint4*)(tb + s * 8 + 4);
                uint4 l0 = *(const uint4*)(tb + 32 + s * 8);
                uint4 l1 = *(const uint4*)(tb + 32 + s * 8 + 4);
                uint32_t bh[8] = { h0.x, h0.y, h0.z, h0.w, h1.x, h1.y, h1.z, h1.w };
                uint32_t bl[8] = { l0.x, l0.y, l0.z, l0.w, l1.x, l1.y, l1.z, l1.w };
#pragma unroll
                for (int nt = 0; nt < 4; nt++) {
#pragma unroll
                    for (int f = 0; f < 2; f++) {
                        mma16816(acc[f][nt], ah[f], bh[2 * nt], bh[2 * nt + 1]);
                        mma16816(acc[f][nt], al[f], bh[2 * nt], bh[2 * nt + 1]);
                        mma16816(acc[f][nt], ah[f], bl[2 * nt], bl[2 * nt + 1]);
                    }
                }
            }
        }
        if (ky < 2) { CP_WAIT0(); }
        __syncthreads();
        buf ^= 1;
    }

    // ---- epilogue: ch-last transpose via smem ----
#pragma unroll
    for (int f = 0; f < 2; f++)
#pragma unroll
        for (int nt = 0; nt < 4; nt++) {
            int m = wm * 32 + f * 16 + (lane >> 2);
            int n = wn * 32 + nt * 8 + (lane & 3) * 2;
            float2 v0 = { acc[f][nt][0] + s_b[n], acc[f][nt][1] + s_b[n + 1] };
            float2 v1 = { acc[f][nt][2] + s_b[n], acc[f][nt][3] + s_b[n + 1] };
            *(float2*)&st[m * 68 + n]       = v0;
            *(float2*)&st[(m + 8) * 68 + n] = v1;
        }
    __syncthreads();

    if (tid < 128) {
        const float* row = &st[tid * 68];
        float v[64];
#pragma unroll
        for (int i = 0; i < 16; i++) {
            float4 f4 = *(const float4*)&row[i * 4];
            v[4 * i] = f4.x; v[4 * i + 1] = f4.y; v[4 * i + 2] = f4.z; v[4 * i + 3] = f4.w;
        }
        uint4* dst;
        if (!IS_CONV2) {
#pragma unroll
            for (int c = 0; c < 64; c++) v[c] = v[c] > 0.f ? v[c] : s_a[c] * v[c];
            dst = (uint4*)(outp + (((size_t)b * PADW + y0 + 1) * PADW + (x0 + 1 + tid)) * 128);
        } else {
            float sum = 0.f, mx = -FLT_MAX;
#pragma unroll
            for (int c = 0; c < 64; c++) { sum += v[c]; mx = fmaxf(mx, v[c]); }
            const int gp = y0 * 256 + x0 + tid;
            g_avg[b * HWN + gp] = sum * (1.0f / CH);
            g_max[b * HWN + gp] = mx;
            dst = (uint4*)(outp + (((size_t)b << 16) + gp) * 128);
        }
#pragma unroll
        for (int j = 0; j < 16; j++) {
            int k0 = (j & 7) * 8;
            bool lo = j >= 8;
            uint4 u; uint32_t* wp = (uint32_t*)&u;
#pragma unroll
            for (int q = 0; q < 4; q++) {
                float f0 = v[k0 + 2 * q], f1 = v[k0 + 2 * q + 1];
                if (lo) {
                    f0 -= __bfloat162float(__float2bfloat16(f0));
                    f1 -= __bfloat162float(__float2bfloat16(f1));
                }
                wp[q] = pack2bf(f0, f1);
            }
            dst[j] = u;
        }
    } else if (IS_CONV2 && tid < 192) {
        int oc = tid - 128;
        float s = 0.0f;
#pragma unroll 8
        for (int p = 0; p < 128; p++) s += st[p * 68 + oc];
        atomicAdd(&g_chansum[b * CH + oc], s);
    }
}

// ---------------- spatial attention conv -------------------------------------
__global__ __launch_bounds__(256)
void sa_kernel(const float* __restrict__ sa_w, const float* __restrict__ sa_b)
{
    int p = blockIdx.x * 256 + threadIdx.x;
    int b = blockIdx.y;
    int x = p & (IMG_W - 1);
    int y = p >> 8;
    float s = sa_b[0];
#pragma unroll
    for (int ky = 0; ky < 3; ky++) {
        int gy = reflect(y + ky - 1, IMG_H);
#pragma unroll
        for (int kx = 0; kx < 3; kx++) {
            int gx = reflect(x + kx - 1, IMG_W);
            int q = b * HWN + gy * IMG_W + gx;
            s = fmaf(sa_w[ky * 3 + kx],     g_avg[q], s);
            s = fmaf(sa_w[9 + ky * 3 + kx], g_max[q], s);
        }
    }
    g_sg[b * HWN + p] = 1.0f / (1.0f + expf(-s));
}

// ---------------- per-batch small dense math + K prepack ---------------------
__global__ __launch_bounds__(256)
void small_kernel(const float* __restrict__ h_in,
                  const float* __restrict__ ca_w1, const float* __restrict__ ca_b1,
                  const float* __restrict__ ca_a,
                  const float* __restrict__ ca_w2, const float* __restrict__ ca_b2,
                  const float* __restrict__ fc_w,  const float* __restrict__ fc_b,
                  const float* __restrict__ k1_w,  const float* __restrict__ k1_b,
                  const float* __restrict__ k2_w,  const float* __restrict__ k2_b,
                  const float* __restrict__ k3_w,  const float* __restrict__ k3_b)
{
    __shared__ float g[64], t1[32], cv[64], hv[16], t0[16], ta[32], tb[32];
    const int b = blockIdx.x;
    const int tid = threadIdx.x;

    if (tid < 64) g[tid] = g_chansum[b * CH + tid] * (1.0f / HWN);
    if (tid < 16) hv[tid] = h_in[b * 16 + tid];
    __syncthreads();

    if (tid < 32) {
        float s = ca_b1[tid];
        for (int c = 0; c < 64; c++) s = fmaf(ca_w1[tid * 64 + c], g[c], s);
        t1[tid] = s > 0.0f ? s : ca_a[tid] * s;
    }
    if (tid >= 32 && tid < 48) {
        int j = tid - 32;
        float s = fc_b[j];
        for (int c = 0; c < 16; c++) s = fmaf(fc_w[j * 16 + c], hv[c], s);
        t0[j] = s >= 0.0f ? s : 0.01f * s;
    }
    __syncthreads();

    if (tid < 64) {
        float s = ca_b2[tid];
        for (int j = 0; j < 32; j++) s = fmaf(ca_w2[tid * 32 + j], t1[j], s);
        cv[tid] = 1.0f / (1.0f + expf(-s));
    }
    if (tid >= 64 && tid < 96) {
        int j = tid - 64;
        float s = k1_b[j];
        for (int c = 0; c < 16; c++) s = fmaf(k1_w[j * 16 + c], t0[c], s);
        ta[j] = s >= 0.0f ? s : 0.01f * s;
    }
    __syncthreads();

    if (tid < 32) {
        float s = k2_b[tid];
        for (int j = 0; j < 32; j++) s = fmaf(k2_w[tid * 32 + j], ta[j], s);
        tb[tid] = s >= 0.0f ? s : 0.01f * s;
    }
    __syncthreads();

    for (int idx = tid; idx < 8192; idx += 256) {
        float s = k3_b[idx];
        for (int j = 0; j < 32; j++) s = fmaf(k3_w[idx * 32 + j], tb[j], s);
        int o = idx >> 7, i = idx & 127;
        int which = (i >= 64);
        int ch = i & 63;
        float val = which ? s * cv[ch] : s;
        __nv_bfloat16 hi = __float2bfloat16(val);
        __nv_bfloat16 lo = __float2bfloat16(val - __bfloat162float(hi));
        size_t base = (size_t)b * 16384 + (which * 64 + o) * 128 + ch;
        g_Kpk[base]      = hi;
        g_Kpk[base + 64] = lo;
    }
}

// ---------------- final: frag-LDG dual matvec + residual ---------------------
#define STP 132
#define FIN_SMEM 34816     // max(slabR 32768, st 64*132*4=33792) + pad

__global__ __launch_bounds__(256)
void final_kernel(const float* __restrict__ hc_bias,
                  const float* __restrict__ x,
                  float* __restrict__ out)
{
    extern __shared__ char smem[];
    char* slabR = smem;                 // 128 px x 256B, swizzled
    float* st   = (float*)smem;         // epilogue reuse
    __shared__ float ssg[128], sbias[64];

    const int tid = threadIdx.x, lane = tid & 31, wid = tid >> 5;
    const int wm = wid & 3, wn = wid >> 2;
    const int b  = blockIdx.y;
    const int p0 = blockIdx.x * 128;
    const uint32_t sr_u = s2u(slabR);

    if (tid < 64) sbias[tid] = hc_bias[tid];
    if (tid < 128) ssg[tid] = g_sg[b * HWN + p0 + tid];

    {
        const char* src = (const char*)(g_rcl + (((size_t)b << 16) + p0) * 128);
        for (int i = tid; i < 2048; i += 256) {
            int p = i >> 4, j = i & 15;
            cp16(sr_u + p * 256 + ((j ^ (p & 7)) << 4), src + i * 16);
        }
        CP_COMMIT(); CP_WAIT0();
    }
    __syncthreads();

    float acc[2][2][4][4];
#pragma unroll
    for (int s = 0; s < 2; s++)
#pragma unroll
        for (int f = 0; f < 2; f++)
#pragma unroll
            for (int g = 0; g < 4; g++)
#pragma unroll
                for (int c = 0; c < 4; c++) acc[s][f][g][c] = 0.0f;

    const uint32_t* kb0 = g_Kfrag + (((size_t)(b * 2 + 0) * 2 + wn) * 32 + lane) * 64;
    const uint32_t* kb1 = g_Kfrag + (((size_t)(b * 2 + 1) * 2 + wn) * 32 + lane) * 64;

#pragma unroll
    for (int s = 0; s < 4; s++) {
        uint32_t ah[2][4], al[2][4];
#pragma unroll
        for (int f = 0; f < 2; f++) {
            int row = wm * 32 + f * 16 + (lane & 15);
            uint32_t chi = (uint32_t)(s * 2 + (lane >> 4));
            uint32_t base = sr_u + row * 256;
            ldsm_x4(base + (((chi    ) ^ (row & 7)) << 4),
                    ah[f][0], ah[f][1], ah[f][2], ah[f][3]);
            ldsm_x4(base + (((chi + 8) ^ (row & 7)) << 4),
                    al[f][0], al[f][1], al[f][2], al[f][3]);
        }
#pragma unroll
        for (int set = 0; set < 2; set++) {
            const uint32_t* kb = set ? kb1 : kb0;
            uint4 h0 = *(const uint4*)(kb + s * 8);
            uint4 h1 = *(const uint4*)(kb + s * 8 + 4);
            uint4 l0 = *(const uint4*)(kb + 32 + s * 8);
            uint4 l1 = *(const uint4*)(kb + 32 + s * 8 + 4);
            uint32_t bh[8] = { h0.x, h0.y, h0.z, h0.w, h1.x, h1.y, h1.z, h1.w };
            uint32_t bl[8] = { l0.x, l0.y, l0.z, l0.w, l1.x, l1.y, l1.z, l1.w };
#pragma unroll
            for (int nt = 0; nt < 4; nt++) {
#pragma unroll
                for (int f = 0; f < 2; f++) {
                    mma16816(acc[set][f][nt], ah[f], bh[2 * nt], bh[2 * nt + 1]);
                    mma16816(acc[set][f][nt], al[f], bh[2 * nt], bh[2 * nt + 1]);
                    mma16816(acc[set][f][nt], ah[f], bl[2 * nt], bl[2 * nt + 1]);
                }
            }
        }
    }

    __syncthreads();
#pragma unroll
    for (int f = 0; f < 2; f++)
#pragma unroll
        for (int nt = 0; nt < 4; nt++) {
#pragma unroll
            for (int c = 0; c < 4; c++) {
                int m = wm * 32 + f * 16 + (lane >> 2) + ((c >> 1) << 3);
                int n = wn * 32 + nt * 8 + ((lane & 3) << 1) + (c & 1);
                st[n * STP + m] = ssg[m] * acc[0][f][nt][c] + acc[1][f][nt][c] + sbias[n];
            }
        }
    __syncthreads();

    const size_t obase = (size_t)b * CH * HWN + p0;
    for (int idx = tid; idx < 2048; idx += 256) {
        int oc = idx >> 5, v = (idx & 31) << 2;
        size_t gi = obase + (size_t)oc * HWN + v;
        float4 xv = *(const float4*)&x[gi];
        float4 sv = *(const float4*)&st[oc * STP + v];
        float4 ov = { xv.x + sv.x, xv.y + sv.y, xv.z + sv.z, xv.w + sv.w };
        *(float4*)&out[gi] = ov;
    }
}

// ---------------- launch ----------------------------------------------------
extern "C" void kernel_launch(void* const* d_in, const int* in_sizes, int n_in,
                              void* d_out, int out_size)
{
    const float* x       = (const float*)d_in[0];
    const float* h       = (const float*)d_in[1];
    const float* conv1_w = (const float*)d_in[2];
    const float* conv1_b = (const float*)d_in[3];
    const float* prelu_a = (const float*)d_in[4];
    const float* conv2_w = (const float*)d_in[5];
    const float* conv2_b = (const float*)d_in[6];
    const float* sa_w    = (const float*)d_in[7];
    const float* sa_b    = (const float*)d_in[8];
    const float* ca_w1   = (const float*)d_in[9];
    const float* ca_b1   = (const float*)d_in[10];
    const float* ca_a    = (const float*)d_in[11];
    const float* ca_w2   = (const float*)d_in[12];
    const float* ca_b2   = (const float*)d_in[13];
    const float* fc_w    = (const float*)d_in[14];
    const float* fc_b    = (const float*)d_in[15];
    const float* k1_w    = (const float*)d_in[16];
    const float* k1_b    = (const float*)d_in[17];
    const float* k2_w    = (const float*)d_in[18];
    const float* k2_b    = (const float*)d_in[19];
    const float* k3_w    = (const float*)d_in[20];
    const float* k3_b    = (const float*)d_in[21];
    const float* hc_bias = (const float*)d_in[22];
    float* out = (float*)d_out;

    __nv_bfloat16 *padx = nullptr, *pad1 = nullptr, *rcl = nullptr;
    uint32_t* wfr = nullptr;
    cudaGetSymbolAddress((void**)&padx, g_padx);
    cudaGetSymbolAddress((void**)&pad1, g_pad1);
    cudaGetSymbolAddress((void**)&rcl,  g_rcl);
    cudaGetSymbolAddress((void**)&wfr,  g_Wfrag);

    static bool attr_set = false;
    if (!attr_set) {
        cudaFuncSetAttribute(conv_frag_kernel<false>,
                             cudaFuncAttributeMaxDynamicSharedMemorySize, CONV_SMEM);
        cudaFuncSetAttribute(conv_frag_kernel<true>,
                             cudaFuncAttributeMaxDynamicSharedMemorySize, CONV_SMEM);
        cudaFuncSetAttribute(final_kernel,
                             cudaFuncAttributeMaxDynamicSharedMemorySize, FIN_SMEM);
        attr_set = true;
    }

    init_kernel<<<2, 256>>>();
    wfrag_kernel<<<288, 256>>>(conv1_w, conv2_w);
    pad_input_kernel<<<dim3(256, NB), 256>>>(x);
    border_kernel<<<NB, 256>>>(padx);

    dim3 cgrid(2, 256, NB);
    conv_frag_kernel<false><<<cgrid, 256, CONV_SMEM>>>(padx, wfr,         conv1_b, prelu_a, pad1);
    border_kernel<<<NB, 256>>>(pad1);
    conv_frag_kernel<true ><<<cgrid, 256, CONV_SMEM>>>(pad1, wfr + 36864, conv2_b, prelu_a, rcl);

    sa_kernel<<<dim3(HWN / 256, NB), 256>>>(sa_w, sa_b);

    small_kernel<<<NB, 256>>>(h, ca_w1, ca_b1, ca_a, ca_w2, ca_b2,
                              fc_w, fc_b, k1_w, k1_b, k2_w, k2_b, k3_w, k3_b);
    kfrag_kernel<<<256, 256>>>();

    final_kernel<<<dim3(HWN / 128, NB), 256, FIN_SMEM>>>(hc_bias, x, out);
}

// round 7
// speedup vs baseline: 1.3766x; 1.3766x over previous
#include <cuda_runtime.h>
#include <cuda_bf16.h>
#include <math.h>
#include <float.h>
#include <stdint.h>

#define CH   64
#define IMG_W 256
#define IMG_H 256
#define HWN  65536
#define NB   8

// ---------------- scratch ----------------------------------------------------
__device__ __align__(16) float g_r1[NB * CH * HWN];
__device__ __align__(16) float g_r [NB * CH * HWN];
__device__ __align__(16) float g_avg[NB * HWN];
__device__ __align__(16) float g_max[NB * HWN];
__device__ __align__(16) float g_sg [NB * HWN];
__device__ float g_chansum[NB * CH];
__device__ __align__(16) __nv_bfloat16 g_Kpk[NB * 2 * 64 * 128];   // [b][set*64+oc][ch-hi|ch-lo]
__device__ __align__(16) __nv_bfloat16 g_Wpack[2 * 9 * 2 * 64 * 64];

__device__ __forceinline__ int reflect(int v, int n) {
    if (v < 0) v = -v;
    if (v >= n) v = 2 * n - 2 - v;
    return v;
}
__device__ __forceinline__ uint32_t s2u(const void* p) {
    return (uint32_t)__cvta_generic_to_shared(p);
}
__device__ __forceinline__ void ldsm_x4(uint32_t addr, uint32_t& r0, uint32_t& r1,
                                        uint32_t& r2, uint32_t& r3) {
    asm volatile("ldmatrix.sync.aligned.m8n8.x4.shared.b16 {%0,%1,%2,%3}, [%4];"
                 : "=r"(r0), "=r"(r1), "=r"(r2), "=r"(r3) : "r"(addr));
}
__device__ __forceinline__ void ldsm_x2(uint32_t addr, uint32_t& r0, uint32_t& r1) {
    asm volatile("ldmatrix.sync.aligned.m8n8.x2.shared.b16 {%0,%1}, [%2];"
                 : "=r"(r0), "=r"(r1) : "r"(addr));
}
__device__ __forceinline__ void mma16816(float* c, uint32_t a0, uint32_t a1,
                                         uint32_t a2, uint32_t a3,
                                         uint32_t b0, uint32_t b1) {
    asm volatile("mma.sync.aligned.m16n8k16.row.col.f32.bf16.bf16.f32 "
                 "{%0,%1,%2,%3}, {%4,%5,%6,%7}, {%8,%9}, {%0,%1,%2,%3};"
                 : "+f"(c[0]), "+f"(c[1]), "+f"(c[2]), "+f"(c[3])
                 : "r"(a0), "r"(a1), "r"(a2), "r"(a3), "r"(b0), "r"(b1));
}
__device__ __forceinline__ void mma16816a(float* c, const uint32_t* a,
                                          uint32_t b0, uint32_t b1) {
    mma16816(c, a[0], a[1], a[2], a[3], b0, b1);
}

// ---------------- init ----------------
__global__ void init_kernel() {
    int i = blockIdx.x * blockDim.x + threadIdx.x;
    if (i < NB * CH) g_chansum[i] = 0.0f;
}

// ---------------- weight prepack: fp32 OIHW -> bf16 hi/lo -------------------
__global__ __launch_bounds__(256)
void wpack_kernel(const float* __restrict__ w1, const float* __restrict__ w2) {
    int idx = blockIdx.x * 256 + threadIdx.x;       // < 73728
    if (idx >= 73728) return;
    int ch5 = idx & 31;
    int r   = idx >> 5;        // (((cv*9+t)*2+c2)*64 + oc)
    int oc  = r & 63;
    int r2  = r >> 6;
    int c2  = r2 & 1;
    int r3  = r2 >> 1;
    int t   = r3 % 9;
    int cv  = r3 / 9;
    const float* w = cv ? w2 : w1;
    float v = w[oc * 576 + (c2 * 32 + ch5) * 9 + t];
    __nv_bfloat16 hi = __float2bfloat16(v);
    __nv_bfloat16 lo = __float2bfloat16(v - __bfloat162float(hi));
    __nv_bfloat16* dst = g_Wpack + (size_t)r * 64;
    dst[ch5]      = hi;
    dst[32 + ch5] = lo;
}

// ---------------- tensor-core 3x3 conv (R3 version, verbatim) ---------------
#define PK 72
#define PW 72
#define WOFF 56320
#define SMEM_BYTES 65536

template <bool IS_CONV2>
__global__ __launch_bounds__(256)
void conv_mma_kernel(const float* __restrict__ in,
                     const __nv_bfloat16* __restrict__ wpack,
                     const float* __restrict__ bias,
                     const float* __restrict__ prelu_a,
                     float* __restrict__ out)
{
    extern __shared__ char smem[];
    __nv_bfloat16* slab = (__nv_bfloat16*)smem;            // 390 rows x PK
    __nv_bfloat16* wbuf = (__nv_bfloat16*)(smem + WOFF);   // 64 rows x PW
    float* st = (float*)smem;                              // epilogue reuse
    __shared__ float sbias[64], sact[64];

    const int tid  = threadIdx.x;
    const int lane = tid & 31;
    const int wid  = tid >> 5;
    const int wm   = wid & 3;
    const int wn   = wid >> 2;
    const int x0   = blockIdx.x * 128;
    const int y0   = blockIdx.y;
    const int b    = blockIdx.z;

    if (tid < 64) { sbias[tid] = bias[tid]; sact[tid] = IS_CONV2 ? 0.f : prelu_a[tid]; }

    float acc[2][4][4];
#pragma unroll
    for (int f = 0; f < 2; f++)
#pragma unroll
        for (int g = 0; g < 4; g++)
#pragma unroll
            for (int c = 0; c < 4; c++) acc[f][g][c] = 0.0f;

    const uint32_t slab_u = s2u(slab);
    const uint32_t wbuf_u = s2u(wbuf);

    for (int c2 = 0; c2 < 2; c2++) {
        __syncthreads();
        for (int idx = tid; idx < 32 * 390; idx += 256) {
            int ch  = idx / 390;
            int rem = idx - ch * 390;
            int r3  = rem / 130;
            int i   = rem - r3 * 130;
            int ry  = reflect(y0 + r3 - 1, IMG_H);
            int rx  = reflect(x0 + i - 1, IMG_W);
            float v = in[((size_t)(b * CH + c2 * 32 + ch)) * HWN + ry * IMG_W + rx];
            __nv_bfloat16 hi = __float2bfloat16(v);
            __nv_bfloat16 lo = __float2bfloat16(v - __bfloat162float(hi));
            int row = r3 * 130 + i;
            slab[row * PK + ch]      = hi;
            slab[row * PK + 32 + ch] = lo;
        }
        for (int t = 0; t < 9; t++) {
            __syncthreads();
            const __nv_bfloat16* wsrc = wpack + (((size_t)t * 2 + c2) << 12);
            for (int idx = tid; idx < 4096; idx += 256)
                wbuf[(idx >> 6) * PW + (idx & 63)] = wsrc[idx];
            __syncthreads();

            const int dy = t / 3 - 1;
            const int dx = t - (t / 3) * 3 - 1;
            const int rowbase = (dy + 1) * 130 + dx + 1;
#pragma unroll
            for (int s = 0; s < 3; s++) {
                const int Aoff = (s == 1) ? 32 : 0;
                const int Woff = (s == 2) ? 32 : 0;
#pragma unroll
                for (int ks = 0; ks < 32; ks += 16) {
                    uint32_t a[2][4];
#pragma unroll
                    for (int f = 0; f < 2; f++) {
                        int row = rowbase + wm * 32 + f * 16 + (lane & 15);
                        uint32_t addr = slab_u +
                            (uint32_t)((row * PK + Aoff + ks + ((lane >> 4) << 3)) * 2);
                        ldsm_x4(addr, a[f][0], a[f][1], a[f][2], a[f][3]);
                    }
#pragma unroll
                    for (int g = 0; g < 4; g++) {
                        uint32_t b0, b1;
                        int nrow = wn * 32 + g * 8 + (lane & 7);
                        uint32_t addr = wbuf_u +
                            (uint32_t)((nrow * PW + Woff + ks + (((lane >> 3) & 1) << 3)) * 2);
                        ldsm_x2(addr, b0, b1);
                        mma16816(acc[0][g], a[0][0], a[0][1], a[0][2], a[0][3], b0, b1);
                        mma16816(acc[1][g], a[1][0], a[1][1], a[1][2], a[1][3], b0, b1);
                    }
                }
            }
        }
    }

    __syncthreads();
#pragma unroll
    for (int f = 0; f < 2; f++)
#pragma unroll
        for (int g = 0; g < 4; g++)
#pragma unroll
            for (int c = 0; c < 4; c++) {
                int m = wm * 32 + f * 16 + (lane >> 2) + ((c >> 1) << 3);
                int n = wn * 32 + g * 8 + ((lane & 3) << 1) + (c & 1);
                st[n * 130 + m] = acc[f][g][c] + sbias[n];
            }
    __syncthreads();

    const size_t obase = (size_t)b * CH * HWN + (size_t)y0 * IMG_W + x0;
    if (!IS_CONV2) {
        for (int j = tid; j < 8192; j += 256) {
            int oc = j >> 7, p = j & 127;
            float v = st[oc * 130 + p];
            v = v > 0.0f ? v : sact[oc] * v;
            out[obase + (size_t)oc * HWN + p] = v;
        }
    } else {
        for (int j = tid; j < 8192; j += 256) {
            int oc = j >> 7, p = j & 127;
            out[obase + (size_t)oc * HWN + p] = st[oc * 130 + p];
        }
        if (tid < 128) {
            int p = tid;
            float s = 0.0f, mx = -FLT_MAX;
#pragma unroll 8
            for (int oc = 0; oc < 64; oc++) {
                float v = st[oc * 130 + p];
                s += v; mx = fmaxf(mx, v);
            }
            g_avg[b * HWN + y0 * IMG_W + x0 + p] = s * (1.0f / CH);
            g_max[b * HWN + y0 * IMG_W + x0 + p] = mx;
        } else if (tid < 192) {
            int oc = tid - 128;
            float s = 0.0f;
#pragma unroll 8
            for (int p = 0; p < 128; p++) s += st[oc * 130 + p];
            atomicAdd(&g_chansum[b * CH + oc], s);
        }
    }
}

// ---------------- spatial attention conv -------------------------------------
__global__ __launch_bounds__(256)
void sa_kernel(const float* __restrict__ sa_w, const float* __restrict__ sa_b)
{
    int p = blockIdx.x * 256 + threadIdx.x;
    int b = blockIdx.y;
    int x = p & (IMG_W - 1);
    int y = p >> 8;
    float s = sa_b[0];
#pragma unroll
    for (int ky = 0; ky < 3; ky++) {
        int gy = reflect(y + ky - 1, IMG_H);
#pragma unroll
        for (int kx = 0; kx < 3; kx++) {
            int gx = reflect(x + kx - 1, IMG_W);
            int q = b * HWN + gy * IMG_W + gx;
            s = fmaf(sa_w[ky * 3 + kx],     g_avg[q], s);
            s = fmaf(sa_w[9 + ky * 3 + kx], g_max[q], s);
        }
    }
    g_sg[b * HWN + p] = 1.0f / (1.0f + expf(-s));
}

// ---------------- per-batch small dense math + K prepack ---------------------
__global__ __launch_bounds__(256)
void small_kernel(const float* __restrict__ h_in,
                  const float* __restrict__ ca_w1, const float* __restrict__ ca_b1,
                  const float* __restrict__ ca_a,
                  const float* __restrict__ ca_w2, const float* __restrict__ ca_b2,
                  const float* __restrict__ fc_w,  const float* __restrict__ fc_b,
                  const float* __restrict__ k1_w,  const float* __restrict__ k1_b,
                  const float* __restrict__ k2_w,  const float* __restrict__ k2_b,
                  const float* __restrict__ k3_w,  const float* __restrict__ k3_b)
{
    __shared__ float g[64], t1[32], cv[64], hv[16], t0[16], ta[32], tb[32];
    const int b = blockIdx.x;
    const int tid = threadIdx.x;

    if (tid < 64) g[tid] = g_chansum[b * CH + tid] * (1.0f / HWN);
    if (tid < 16) hv[tid] = h_in[b * 16 + tid];
    __syncthreads();

    if (tid < 32) {
        float s = ca_b1[tid];
        for (int c = 0; c < 64; c++) s = fmaf(ca_w1[tid * 64 + c], g[c], s);
        t1[tid] = s > 0.0f ? s : ca_a[tid] * s;
    }
    if (tid >= 32 && tid < 48) {
        int j = tid - 32;
        float s = fc_b[j];
        for (int c = 0; c < 16; c++) s = fmaf(fc_w[j * 16 + c], hv[c], s);
        t0[j] = s >= 0.0f ? s : 0.01f * s;
    }
    __syncthreads();

    if (tid < 64) {
        float s = ca_b2[tid];
        for (int j = 0; j < 32; j++) s = fmaf(ca_w2[tid * 32 + j], t1[j], s);
        cv[tid] = 1.0f / (1.0f + expf(-s));
    }
    if (tid >= 64 && tid < 96) {
        int j = tid - 64;
        float s = k1_b[j];
        for (int c = 0; c < 16; c++) s = fmaf(k1_w[j * 16 + c], t0[c], s);
        ta[j] = s >= 0.0f ? s : 0.01f * s;
    }
    __syncthreads();

    if (tid < 32) {
        float s = k2_b[tid];
        for (int j = 0; j < 32; j++) s = fmaf(k2_w[tid * 32 + j], ta[j], s);
        tb[tid] = s >= 0.0f ? s : 0.01f * s;
    }
    __syncthreads();

    for (int idx = tid; idx < 8192; idx += 256) {
        float s = k3_b[idx];
        for (int j = 0; j < 32; j++) s = fmaf(k3_w[idx * 32 + j], tb[j], s);
        int o = idx >> 7, i = idx & 127;
        int which = (i >= 64);
        int ch = i & 63;
        float val = which ? s * cv[ch] : s;
        __nv_bfloat16 hi = __float2bfloat16(val);
        __nv_bfloat16 lo = __float2bfloat16(val - __bfloat162float(hi));
        size_t base = (size_t)b * 16384 + (which * 64 + o) * 128 + ch;
        g_Kpk[base]      = hi;
        g_Kpk[base + 64] = lo;
    }
}

// ---------------- final: tensor-core dual matvec + residual ------------------
#define PF  136
#define STP 132
#define KM_B   34816
#define SLR_B  34816
#define FIN_SMEM (KM_B + SLR_B + 512)

__global__ __launch_bounds__(256)
void final_kernel(const float* __restrict__ hc_bias,
                  const float* __restrict__ x,
                  float* __restrict__ out)
{
    extern __shared__ char smem[];
    __nv_bfloat16* sKm   = (__nv_bfloat16*)smem;              // [128 rows][PF]
    __nv_bfloat16* slabR = (__nv_bfloat16*)(smem + KM_B);     // [128 px][PF]
    float* ssg = (float*)(smem + KM_B + SLR_B);               // [128]
    float* st  = (float*)smem;                                // epilogue reuse
    __shared__ float sbias[64];

    const int tid  = threadIdx.x;
    const int lane = tid & 31;
    const int wid  = tid >> 5;
    const int wm   = wid & 3;
    const int wn   = wid >> 2;
    const int b    = blockIdx.y;
    const int p0   = blockIdx.x * 128;

    if (tid < 64) sbias[tid] = hc_bias[tid];
    const __nv_bfloat16* ksrc = g_Kpk + (size_t)b * 16384;
    for (int idx = tid; idx < 2048; idx += 256) {
        int r = idx >> 4, v = (idx & 15) << 3;
        *(uint4*)(sKm + r * PF + v) = *(const uint4*)(ksrc + r * 128 + v);
    }
    for (int idx = tid; idx < 2048; idx += 256) {
        int ch = idx >> 5, v = idx & 31;
        float4 f4 = *(const float4*)&g_r[((size_t)(b * CH + ch)) * HWN + p0 + 4 * v];
        float vals[4] = { f4.x, f4.y, f4.z, f4.w };
#pragma unroll
        for (int e = 0; e < 4; e++) {
            int px = 4 * v + e;
            __nv_bfloat16 hi = __float2bfloat16(vals[e]);
            slabR[px * PF + ch]      = hi;
            slabR[px * PF + 64 + ch] = __float2bfloat16(vals[e] - __bfloat162float(hi));
        }
    }
    if (tid < 128) ssg[tid] = g_sg[b * HWN + p0 + tid];
    __syncthreads();

    const uint32_t km_u = s2u(sKm);
    const uint32_t sr_u = s2u(slabR);
    const int acol  = (lane >> 4) << 3;
    const uint32_t abase = sr_u + (uint32_t)(((wm * 32 + (lane & 15)) * PF + acol) * 2);
    const int bg    = lane >> 4;
    const int bk    = ((lane >> 3) & 1) << 3;
    const int blrow = lane & 7;

    float acc[2][2][4][4];
#pragma unroll
    for (int s = 0; s < 2; s++)
#pragma unroll
        for (int f = 0; f < 2; f++)
#pragma unroll
            for (int g = 0; g < 4; g++)
#pragma unroll
                for (int c = 0; c < 4; c++) acc[s][f][g][c] = 0.0f;

#pragma unroll
    for (int ks = 0; ks < 4; ks++) {
        uint32_t ah[2][4], al[2][4];
#pragma unroll
        for (int f = 0; f < 2; f++) {
            uint32_t ad = abase + (uint32_t)(((f * 16) * PF + ks * 16) * 2);
            ldsm_x4(ad,       ah[f][0], ah[f][1], ah[f][2], ah[f][3]);
            ldsm_x4(ad + 128, al[f][0], al[f][1], al[f][2], al[f][3]);
        }
#pragma unroll
        for (int s = 0; s < 2; s++) {
#pragma unroll
            for (int gp = 0; gp < 2; gp++) {
                int brow = s * 64 + wn * 32 + (2 * gp + bg) * 8 + blrow;
                uint32_t bb = km_u + (uint32_t)((brow * PF + bk + ks * 16) * 2);
                uint32_t bh0, bh1, bh2, bh3, bl0, bl1, bl2, bl3;
                ldsm_x4(bb,       bh0, bh1, bh2, bh3);
                ldsm_x4(bb + 128, bl0, bl1, bl2, bl3);
#pragma unroll
                for (int f = 0; f < 2; f++) {
                    mma16816a(acc[s][f][2 * gp],     ah[f], bh0, bh1);
                    mma16816a(acc[s][f][2 * gp],     al[f], bh0, bh1);
                    mma16816a(acc[s][f][2 * gp],     ah[f], bl0, bl1);
                    mma16816a(acc[s][f][2 * gp + 1], ah[f], bh2, bh3);
                    mma16816a(acc[s][f][2 * gp + 1], al[f], bh2, bh3);
                    mma16816a(acc[s][f][2 * gp + 1], ah[f], bl2, bl3);
                }
            }
        }
    }

    __syncthreads();
#pragma unroll
    for (int f = 0; f < 2; f++)
#pragma unroll
        for (int g = 0; g < 4; g++)
#pragma unroll
            for (int c = 0; c < 4; c++) {
                int m = wm * 32 + f * 16 + (lane >> 2) + ((c >> 1) << 3);
                int n = wn * 32 + g * 8 + ((lane & 3) << 1) + (c & 1);
                st[n * STP + m] = ssg[m] * acc[0][f][g][c] + acc[1][f][g][c] + sbias[n];
            }
    __syncthreads();

    const size_t obase = (size_t)b * CH * HWN + p0;
    for (int idx = tid; idx < 2048; idx += 256) {
        int oc = idx >> 5, v = (idx & 31) << 2;
        size_t gi = obase + (size_t)oc * HWN + v;
        float4 xv = *(const float4*)&x[gi];
        float4 sv = *(const float4*)&st[oc * STP + v];
        float4 ov = { xv.x + sv.x, xv.y + sv.y, xv.z + sv.z, xv.w + sv.w };
        *(float4*)&out[gi] = ov;
    }
}

// ---------------- launch ----------------------------------------------------
extern "C" void kernel_launch(void* const* d_in, const int* in_sizes, int n_in,
                              void* d_out, int out_size)
{
    const float* x       = (const float*)d_in[0];
    const float* h       = (const float*)d_in[1];
    const float* conv1_w = (const float*)d_in[2];
    const float* conv1_b = (const float*)d_in[3];
    const float* prelu_a = (const float*)d_in[4];
    const float* conv2_w = (const float*)d_in[5];
    const float* conv2_b = (const float*)d_in[6];
    const float* sa_w    = (const float*)d_in[7];
    const float* sa_b    = (const float*)d_in[8];
    const float* ca_w1   = (const float*)d_in[9];
    const float* ca_b1   = (const float*)d_in[10];
    const float* ca_a    = (const float*)d_in[11];
    const float* ca_w2   = (const float*)d_in[12];
    const float* ca_b2   = (const float*)d_in[13];
    const float* fc_w    = (const float*)d_in[14];
    const float* fc_b    = (const float*)d_in[15];
    const float* k1_w    = (const float*)d_in[16];
    const float* k1_b    = (const float*)d_in[17];
    const float* k2_w    = (const float*)d_in[18];
    const float* k2_b    = (const float*)d_in[19];
    const float* k3_w    = (const float*)d_in[20];
    const float* k3_b    = (const float*)d_in[21];
    const float* hc_bias = (const float*)d_in[22];
    float* out = (float*)d_out;

    float* r1 = nullptr;
    float* r  = nullptr;
    __nv_bfloat16* wpk = nullptr;
    cudaGetSymbolAddress((void**)&r1,  g_r1);
    cudaGetSymbolAddress((void**)&r,   g_r);
    cudaGetSymbolAddress((void**)&wpk, g_Wpack);

    static bool attr_set = false;
    if (!attr_set) {
        cudaFuncSetAttribute(conv_mma_kernel<false>,
                             cudaFuncAttributeMaxDynamicSharedMemorySize, SMEM_BYTES);
        cudaFuncSetAttribute(conv_mma_kernel<true>,
                             cudaFuncAttributeMaxDynamicSharedMemorySize, SMEM_BYTES);
        cudaFuncSetAttribute(final_kernel,
                             cudaFuncAttributeMaxDynamicSharedMemorySize, FIN_SMEM);
        attr_set = true;
    }

    init_kernel<<<2, 256>>>();
    wpack_kernel<<<288, 256>>>(conv1_w, conv2_w);

    dim3 cgrid(IMG_W / 128, IMG_H, NB);
    conv_mma_kernel<false><<<cgrid, 256, SMEM_BYTES>>>(x,  wpk,         conv1_b, prelu_a, r1);
    conv_mma_kernel<true ><<<cgrid, 256, SMEM_BYTES>>>(r1, wpk + 73728, conv2_b, prelu_a, r);

    sa_kernel<<<dim3(HWN / 256, NB), 256>>>(sa_w, sa_b);

    small_kernel<<<NB, 256>>>(h, ca_w1, ca_b1, ca_a, ca_w2, ca_b2,
                              fc_w, fc_b, k1_w, k1_b, k2_w, k2_b, k3_w, k3_b);

    final_kernel<<<dim3(HWN / 128, NB), 256, FIN_SMEM>>>(hc_bias, x, out);
}

// round 8
// speedup vs baseline: 2.0465x; 1.4866x over previous
#include <cuda_runtime.h>
#include <cuda_bf16.h>
#include <math.h>
#include <float.h>
#include <stdint.h>

#define CH    64
#define IMG_W 256
#define IMG_H 256
#define HWN   65536
#define NB    8
#define PADW  258

// ---------------- device-global scratch -------------------------------------
__device__ __align__(16) __nv_bfloat16 g_padx[NB * PADW * PADW * 128];
__device__ __align__(16) __nv_bfloat16 g_pad1[NB * PADW * PADW * 128];
__device__ __align__(16) __nv_bfloat16 g_rcl [NB * HWN * 128];
__device__ __align__(16) float g_avg[NB * HWN];
__device__ __align__(16) float g_max[NB * HWN];
__device__ __align__(16) float g_sg [NB * HWN];
__device__ float g_chansum[NB * CH];
__device__ __align__(16) __nv_bfloat16 g_Kpk[NB * 2 * 64 * 128];
__device__ __align__(16) uint32_t g_Wfrag[73728];   // [cv][t][wn][sb][ks][h][lane][e]

// ---------------- helpers ----------------------------------------------------
__device__ __forceinline__ int reflect(int v, int n) {
    if (v < 0) v = -v;
    if (v >= n) v = 2 * n - 2 - v;
    return v;
}
__device__ __forceinline__ uint32_t s2u(const void* p) {
    return (uint32_t)__cvta_generic_to_shared(p);
}
__device__ __forceinline__ uint32_t pack2bf(float a, float b) {
    return ((uint32_t)__bfloat16_as_ushort(__float2bfloat16(a))) |
           ((uint32_t)__bfloat16_as_ushort(__float2bfloat16(b)) << 16);
}
__device__ __forceinline__ void ldsm_x4(uint32_t addr, uint32_t& r0, uint32_t& r1,
                                        uint32_t& r2, uint32_t& r3) {
    asm volatile("ldmatrix.sync.aligned.m8n8.x4.shared.b16 {%0,%1,%2,%3}, [%4];"
                 : "=r"(r0), "=r"(r1), "=r"(r2), "=r"(r3) : "r"(addr));
}
__device__ __forceinline__ void mma16816(float* c, const uint32_t* a,
                                         uint32_t b0, uint32_t b1) {
    asm volatile("mma.sync.aligned.m16n8k16.row.col.f32.bf16.bf16.f32 "
                 "{%0,%1,%2,%3}, {%4,%5,%6,%7}, {%8,%9}, {%0,%1,%2,%3};"
                 : "+f"(c[0]), "+f"(c[1]), "+f"(c[2]), "+f"(c[3])
                 : "r"(a[0]), "r"(a[1]), "r"(a[2]), "r"(a[3]), "r"(b0), "r"(b1));
}
__device__ __forceinline__ void cp16(uint32_t dst, const void* src) {
    asm volatile("cp.async.ca.shared.global [%0], [%1], 16;" :: "r"(dst), "l"(src));
}
#define CP_COMMIT() asm volatile("cp.async.commit_group;" ::: "memory")
#define CP_WAIT0()  asm volatile("cp.async.wait_group 0;" ::: "memory")

// ---------------- init ----------------
__global__ void init_kernel() {
    int i = blockIdx.x * blockDim.x + threadIdx.x;
    if (i < NB * CH) g_chansum[i] = 0.0f;
}

// ---------------- weight frag prepack (lane-fastest, coalesced) --------------
__global__ __launch_bounds__(256)
void wfrag_kernel(const float* __restrict__ w1, const float* __restrict__ w2) {
    int idx = blockIdx.x * 256 + threadIdx.x;
    if (idx >= 73728) return;
    int e    = idx & 3;
    int lane = (idx >> 2) & 31;
    int h    = (idx >> 7) & 1;
    int ks   = (idx >> 8) & 3;
    int sb   = (idx >> 10) & 1;
    int wn   = (idx >> 11) & 1;
    int rest = idx >> 12;
    int t    = rest % 9;
    int cv   = rest / 9;
    int nt = 2 * h + (e >> 1);
    int rr = e & 1;
    int n  = wn * 32 + nt * 8 + (lane >> 2);
    int k0 = ks * 16 + rr * 8 + (lane & 3) * 2;
    const float* w = cv ? w2 : w1;
    uint32_t out = 0;
#pragma unroll
    for (int q = 0; q < 2; q++) {
        int ch = k0 + q;
        float v = w[n * 576 + ch * 9 + t];
        __nv_bfloat16 hi = __float2bfloat16(v);
        __nv_bfloat16 bf = sb ? __float2bfloat16(v - __bfloat162float(hi)) : hi;
        out |= ((uint32_t)__bfloat16_as_ushort(bf)) << (16 * q);
    }
    g_Wfrag[idx] = out;
}

// ---------------- input prepass: fp32 NCHW -> padded ch-last bf16 hi/lo ------
__global__ __launch_bounds__(256)
void pad_input_kernel(const float* __restrict__ x) {
    const int y = blockIdx.x, b = blockIdx.y, px = threadIdx.x;
    float v[64];
#pragma unroll
    for (int c = 0; c < 64; c++)
        v[c] = x[(((size_t)(b * 64 + c)) << 16) + y * 256 + px];
    uint4* dst = (uint4*)(g_padx + (((size_t)b * PADW + y + 1) * PADW + px + 1) * 128);
#pragma unroll
    for (int j = 0; j < 16; j++) {
        int k0 = (j & 7) * 8;
        bool lo = j >= 8;
        uint4 u; uint32_t* wp = (uint32_t*)&u;
#pragma unroll
        for (int q = 0; q < 4; q++) {
            float f0 = v[k0 + 2 * q], f1 = v[k0 + 2 * q + 1];
            if (lo) {
                f0 -= __bfloat162float(__float2bfloat16(f0));
                f1 -= __bfloat162float(__float2bfloat16(f1));
            }
            wp[q] = pack2bf(f0, f1);
        }
        dst[j] = u;
    }
}

// ---------------- border fill (reflect), split + wide-grid -------------------
__global__ __launch_bounds__(256)
void border_cols_kernel(__nv_bfloat16* __restrict__ pad) {
    const int b = blockIdx.x;
    int i = blockIdx.y * 256 + threadIdx.x;     // < 8192
    uint4* base = (uint4*)(pad + (size_t)b * PADW * PADW * 128);
    int j = i & 15, which = (i >> 4) & 1, py = 1 + (i >> 5);
    int sp = which ? 255 : 2, dp = which ? 257 : 0;
    base[((size_t)py * PADW + dp) * 16 + j] = base[((size_t)py * PADW + sp) * 16 + j];
}
__global__ __launch_bounds__(256)
void border_rows_kernel(__nv_bfloat16* __restrict__ pad) {
    const int b = blockIdx.x;
    int i = blockIdx.y * 256 + threadIdx.x;     // < 8256
    if (i >= 8256) return;
    uint4* base = (uint4*)(pad + (size_t)b * PADW * PADW * 128);
    int j = i & 15, which = (i >> 4) & 1, px = (i >> 5);
    int sp = which ? 255 : 2, dp = which ? 257 : 0;
    base[((size_t)dp * PADW + px) * 16 + j] = base[((size_t)sp * PADW + px) * 16 + j];
}

// ---------------- conv: mma.sync + frag-LDG weights + cp.async strips --------
#define STRIP_B 33280     // 130 records x 256B (also reused as st: 64*130*4 = 33280)

template <bool IS_CONV2>
__global__ __launch_bounds__(256, 3)
void conv_frag_kernel(const __nv_bfloat16* __restrict__ pad,
                      const uint32_t* __restrict__ wfrag,
                      const float* __restrict__ bias,
                      const float* __restrict__ prelu_a,
                      __nv_bfloat16* __restrict__ outp)
{
    extern __shared__ char smem[];
    float* st = (float*)smem;
    __shared__ float s_b[64], s_a[64];

    const int tid = threadIdx.x, lane = tid & 31, wid = tid >> 5;
    const int wm = wid & 3, wn = wid >> 2;
    const int x0 = blockIdx.x * 128, y0 = blockIdx.y, b = blockIdx.z;
    const uint32_t su = s2u(smem);

    if (tid < 64) { s_b[tid] = bias[tid]; s_a[tid] = IS_CONV2 ? 0.f : prelu_a[tid]; }

    float acc[2][4][4];
#pragma unroll
    for (int f = 0; f < 2; f++)
#pragma unroll
        for (int g = 0; g < 4; g++)
#pragma unroll
            for (int c = 0; c < 4; c++) acc[f][g][c] = 0.0f;

    const int mrow = wm * 32 + (lane & 15);
    const int asel = lane >> 4;
    const uint4* wf4 = (const uint4*)wfrag;

#pragma unroll
    for (int ky = 0; ky < 3; ky++) {
        __syncthreads();
        {
            const char* src = (const char*)(pad +
                (((size_t)b * PADW + (y0 + ky)) * PADW + x0) * 128);
            for (int i = tid; i < 2080; i += 256) {
                int p = i >> 4, j = i & 15;
                cp16(su + p * 256 + ((j ^ (p & 7)) << 4), src + (size_t)i * 16);
            }
            CP_COMMIT(); CP_WAIT0();
        }
        __syncthreads();
#pragma unroll
        for (int kx = 0; kx < 3; kx++) {
            const int t = ky * 3 + kx;
            const uint4* wb = wf4 + ((size_t)(t * 2 + wn) * 16) * 32 + lane;
#pragma unroll
            for (int ks = 0; ks < 4; ks++) {
                uint32_t ah[2][4], al[2][4];
#pragma unroll
                for (int f = 0; f < 2; f++) {
                    int row = kx + f * 16 + mrow;
                    uint32_t base = su + row * 256;
                    int chi = ks * 2 + asel;
                    ldsm_x4(base + (((chi    ) ^ (row & 7)) << 4),
                            ah[f][0], ah[f][1], ah[f][2], ah[f][3]);
                    ldsm_x4(base + (((chi + 8) ^ (row & 7)) << 4),
                            al[f][0], al[f][1], al[f][2], al[f][3]);
                }
                uint4 BH0 = wb[((0 * 4 + ks) * 2 + 0) * 32];
                uint4 BH1 = wb[((0 * 4 + ks) * 2 + 1) * 32];
                uint4 BL0 = wb[((1 * 4 + ks) * 2 + 0) * 32];
                uint4 BL1 = wb[((1 * 4 + ks) * 2 + 1) * 32];
                uint32_t bh[8] = { BH0.x, BH0.y, BH0.z, BH0.w, BH1.x, BH1.y, BH1.z, BH1.w };
                uint32_t bl[8] = { BL0.x, BL0.y, BL0.z, BL0.w, BL1.x, BL1.y, BL1.z, BL1.w };
#pragma unroll
                for (int g = 0; g < 4; g++) {
#pragma unroll
                    for (int f = 0; f < 2; f++) {
                        mma16816(acc[f][g], ah[f], bh[2 * g], bh[2 * g + 1]);
                        mma16816(acc[f][g], al[f], bh[2 * g], bh[2 * g + 1]);
                        mma16816(acc[f][g], ah[f], bl[2 * g], bl[2 * g + 1]);
                    }
                }
            }
        }
    }

    // ---- epilogue: transpose via st, emit ch-last record ----
    __syncthreads();
#pragma unroll
    for (int f = 0; f < 2; f++)
#pragma unroll
        for (int g = 0; g < 4; g++)
#pragma unroll
            for (int c = 0; c < 4; c++) {
                int m = wm * 32 + f * 16 + (lane >> 2) + ((c >> 1) << 3);
                int n = wn * 32 + g * 8 + ((lane & 3) << 1) + (c & 1);
                st[n * 130 + m] = acc[f][g][c] + s_b[n];
            }
    __syncthreads();

    if (tid < 128) {
        float v[64];
#pragma unroll
        for (int c = 0; c < 64; c++) v[c] = st[c * 130 + tid];
        uint4* dst;
        if (!IS_CONV2) {
#pragma unroll
            for (int c = 0; c < 64; c++) v[c] = v[c] > 0.f ? v[c] : s_a[c] * v[c];
            dst = (uint4*)(outp +
                (((size_t)b * PADW + y0 + 1) * PADW + (x0 + 1 + tid)) * 128);
        } else {
            float sum = 0.f, mx = -FLT_MAX;
#pragma unroll
            for (int c = 0; c < 64; c++) { sum += v[c]; mx = fmaxf(mx, v[c]); }
            const int gp = y0 * 256 + x0 + tid;
            g_avg[b * HWN + gp] = sum * (1.0f / CH);
            g_max[b * HWN + gp] = mx;
            dst = (uint4*)(outp + (((size_t)b << 16) + gp) * 128);
        }
#pragma unroll
        for (int j = 0; j < 16; j++) {
            int k0 = (j & 7) * 8;
            bool lo = j >= 8;
            uint4 u; uint32_t* wp = (uint32_t*)&u;
#pragma unroll
            for (int q = 0; q < 4; q++) {
                float f0 = v[k0 + 2 * q], f1 = v[k0 + 2 * q + 1];
                if (lo) {
                    f0 -= __bfloat162float(__float2bfloat16(f0));
                    f1 -= __bfloat162float(__float2bfloat16(f1));
                }
                wp[q] = pack2bf(f0, f1);
            }
            dst[j] = u;
        }
    } else if (IS_CONV2 && tid < 192) {
        int oc = tid - 128;
        float s = 0.0f;
#pragma unroll 8
        for (int p = 0; p < 128; p++) s += st[oc * 130 + p];
        atomicAdd(&g_chansum[b * CH + oc], s);
    }
}

// ---------------- spatial attention conv -------------------------------------
__global__ __launch_bounds__(256)
void sa_kernel(const float* __restrict__ sa_w, const float* __restrict__ sa_b)
{
    int p = blockIdx.x * 256 + threadIdx.x;
    int b = blockIdx.y;
    int x = p & (IMG_W - 1);
    int y = p >> 8;
    float s = sa_b[0];
#pragma unroll
    for (int ky = 0; ky < 3; ky++) {
        int gy = reflect(y + ky - 1, IMG_H);
#pragma unroll
        for (int kx = 0; kx < 3; kx++) {
            int gx = reflect(x + kx - 1, IMG_W);
            int q = b * HWN + gy * IMG_W + gx;
            s = fmaf(sa_w[ky * 3 + kx],     g_avg[q], s);
            s = fmaf(sa_w[9 + ky * 3 + kx], g_max[q], s);
        }
    }
    g_sg[b * HWN + p] = 1.0f / (1.0f + expf(-s));
}

// ---------------- per-batch small dense math + K prepack ---------------------
__global__ __launch_bounds__(256)
void small_kernel(const float* __restrict__ h_in,
                  const float* __restrict__ ca_w1, const float* __restrict__ ca_b1,
                  const float* __restrict__ ca_a,
                  const float* __restrict__ ca_w2, const float* __restrict__ ca_b2,
                  const float* __restrict__ fc_w,  const float* __restrict__ fc_b,
                  const float* __restrict__ k1_w,  const float* __restrict__ k1_b,
                  const float* __restrict__ k2_w,  const float* __restrict__ k2_b,
                  const float* __restrict__ k3_w,  const float* __restrict__ k3_b)
{
    __shared__ float g[64], t1[32], cv[64], hv[16], t0[16], ta[32], tb[32];
    const int b = blockIdx.x;
    const int tid = threadIdx.x;

    if (tid < 64) g[tid] = g_chansum[b * CH + tid] * (1.0f / HWN);
    if (tid < 16) hv[tid] = h_in[b * 16 + tid];
    __syncthreads();

    if (tid < 32) {
        float s = ca_b1[tid];
        for (int c = 0; c < 64; c++) s = fmaf(ca_w1[tid * 64 + c], g[c], s);
        t1[tid] = s > 0.0f ? s : ca_a[tid] * s;
    }
    if (tid >= 32 && tid < 48) {
        int j = tid - 32;
        float s = fc_b[j];
        for (int c = 0; c < 16; c++) s = fmaf(fc_w[j * 16 + c], hv[c], s);
        t0[j] = s >= 0.0f ? s : 0.01f * s;
    }
    __syncthreads();

    if (tid < 64) {
        float s = ca_b2[tid];
        for (int j = 0; j < 32; j++) s = fmaf(ca_w2[tid * 32 + j], t1[j], s);
        cv[tid] = 1.0f / (1.0f + expf(-s));
    }
    if (tid >= 64 && tid < 96) {
        int j = tid - 64;
        float s = k1_b[j];
        for (int c = 0; c < 16; c++) s = fmaf(k1_w[j * 16 + c], t0[c], s);
        ta[j] = s >= 0.0f ? s : 0.01f * s;
    }
    __syncthreads();

    if (tid < 32) {
        float s = k2_b[tid];
        for (int j = 0; j < 32; j++) s = fmaf(k2_w[tid * 32 + j], ta[j], s);
        tb[tid] = s >= 0.0f ? s : 0.01f * s;
    }
    __syncthreads();

    for (int idx = tid; idx < 8192; idx += 256) {
        float s = k3_b[idx];
        for (int j = 0; j < 32; j++) s = fmaf(k3_w[idx * 32 + j], tb[j], s);
        int o = idx >> 7, i = idx & 127;
        int which = (i >= 64);
        int ch = i & 63;
        float val = which ? s * cv[ch] : s;
        __nv_bfloat16 hi = __float2bfloat16(val);
        __nv_bfloat16 lo = __float2bfloat16(val - __bfloat162float(hi));
        size_t base = (size_t)b * 16384 + (which * 64 + o) * 128 + ch;
        g_Kpk[base]      = hi;
        g_Kpk[base + 64] = lo;
    }
}

// ---------------- final: tensor-core dual matvec + residual ------------------
#define PF  136
#define STP 132
#define KM_B   34816
#define SLR_B  32768
#define FIN_SMEM (KM_B + SLR_B + 512)   // 68096

__global__ __launch_bounds__(256)
void final_kernel(const float* __restrict__ hc_bias,
                  const float* __restrict__ x,
                  float* __restrict__ out)
{
    extern __shared__ char smem[];
    __nv_bfloat16* sKm = (__nv_bfloat16*)smem;       // [128 rows][PF]
    char* slabR = smem + KM_B;                       // 128 records x 256B, swizzled
    float* ssg = (float*)(smem + KM_B + SLR_B);      // [128]
    float* st  = (float*)smem;                       // epilogue reuse (33792 <= KM_B)
    __shared__ float sbias[64];

    const int tid  = threadIdx.x;
    const int lane = tid & 31;
    const int wid  = tid >> 5;
    const int wm   = wid & 3;
    const int wn   = wid >> 2;
    const int b    = blockIdx.y;
    const int p0   = blockIdx.x * 128;
    const uint32_t sr_u = s2u(slabR);

    if (tid < 64) sbias[tid] = hc_bias[tid];
    const __nv_bfloat16* ksrc = g_Kpk + (size_t)b * 16384;
    for (int idx = tid; idx < 2048; idx += 256) {
        int r = idx >> 4, v = (idx & 15) << 3;
        *(uint4*)(sKm + r * PF + v) = *(const uint4*)(ksrc + r * 128 + v);
    }
    {
        const char* src = (const char*)(g_rcl + (((size_t)b << 16) + p0) * 128);
        for (int i = tid; i < 2048; i += 256) {
            int p = i >> 4, j = i & 15;
            cp16(sr_u + p * 256 + ((j ^ (p & 7)) << 4), src + (size_t)i * 16);
        }
        CP_COMMIT();
    }
    if (tid < 128) ssg[tid] = g_sg[b * HWN + p0 + tid];
    CP_WAIT0();
    __syncthreads();

    const uint32_t km_u = s2u(sKm);
    const int mrow = wm * 32 + (lane & 15);
    const int asel = lane >> 4;
    const int bg    = lane >> 4;
    const int bk    = ((lane >> 3) & 1) << 3;
    const int blrow = lane & 7;

    float acc[2][2][4][4];
#pragma unroll
    for (int s = 0; s < 2; s++)
#pragma unroll
        for (int f = 0; f < 2; f++)
#pragma unroll
            for (int g = 0; g < 4; g++)
#pragma unroll
                for (int c = 0; c < 4; c++) acc[s][f][g][c] = 0.0f;

#pragma unroll
    for (int ks = 0; ks < 4; ks++) {
        uint32_t ah[2][4], al[2][4];
#pragma unroll
        for (int f = 0; f < 2; f++) {
            int row = mrow + f * 16;
            uint32_t base = sr_u + row * 256;
            int chi = ks * 2 + asel;
            ldsm_x4(base + (((chi    ) ^ (row & 7)) << 4),
                    ah[f][0], ah[f][1], ah[f][2], ah[f][3]);
            ldsm_x4(base + (((chi + 8) ^ (row & 7)) << 4),
                    al[f][0], al[f][1], al[f][2], al[f][3]);
        }
#pragma unroll
        for (int s = 0; s < 2; s++) {
#pragma unroll
            for (int gp = 0; gp < 2; gp++) {
                int brow = s * 64 + wn * 32 + (2 * gp + bg) * 8 + blrow;
                uint32_t bb = km_u + (uint32_t)((brow * PF + bk + ks * 16) * 2);
                uint32_t bh0, bh1, bh2, bh3, bl0, bl1, bl2, bl3;
                ldsm_x4(bb,       bh0, bh1, bh2, bh3);
                ldsm_x4(bb + 128, bl0, bl1, bl2, bl3);
#pragma unroll
                for (int f = 0; f < 2; f++) {
                    mma16816(acc[s][f][2 * gp],     ah[f], bh0, bh1);
                    mma16816(acc[s][f][2 * gp],     al[f], bh0, bh1);
                    mma16816(acc[s][f][2 * gp],     ah[f], bl0, bl1);
                    mma16816(acc[s][f][2 * gp + 1], ah[f], bh2, bh3);
                    mma16816(acc[s][f][2 * gp + 1], al[f], bh2, bh3);
                    mma16816(acc[s][f][2 * gp + 1], ah[f], bl2, bl3);
                }
            }
        }
    }

    __syncthreads();
#pragma unroll
    for (int f = 0; f < 2; f++)
#pragma unroll
        for (int g = 0; g < 4; g++)
#pragma unroll
            for (int c = 0; c < 4; c++) {
                int m = wm * 32 + f * 16 + (lane >> 2) + ((c >> 1) << 3);
                int n = wn * 32 + g * 8 + ((lane & 3) << 1) + (c & 1);
                st[n * STP + m] = ssg[m] * acc[0][f][g][c] + acc[1][f][g][c] + sbias[n];
            }
    __syncthreads();

    const size_t obase = (size_t)b * CH * HWN + p0;
    for (int idx = tid; idx < 2048; idx += 256) {
        int oc = idx >> 5, v = (idx & 31) << 2;
        size_t gi = obase + (size_t)oc * HWN + v;
        float4 xv = *(const float4*)&x[gi];
        float4 sv = *(const float4*)&st[oc * STP + v];
        float4 ov = { xv.x + sv.x, xv.y + sv.y, xv.z + sv.z, xv.w + sv.w };
        *(float4*)&out[gi] = ov;
    }
}

// ---------------- launch ----------------------------------------------------
extern "C" void kernel_launch(void* const* d_in, const int* in_sizes, int n_in,
                              void* d_out, int out_size)
{
    const float* x       = (const float*)d_in[0];
    const float* h       = (const float*)d_in[1];
    const float* conv1_w = (const float*)d_in[2];
    const float* conv1_b = (const float*)d_in[3];
    const float* prelu_a = (const float*)d_in[4];
    const float* conv2_w = (const float*)d_in[5];
    const float* conv2_b = (const float*)d_in[6];
    const float* sa_w    = (const float*)d_in[7];
    const float* sa_b    = (const float*)d_in[8];
    const float* ca_w1   = (const float*)d_in[9];
    const float* ca_b1   = (const float*)d_in[10];
    const float* ca_a    = (const float*)d_in[11];
    const float* ca_w2   = (const float*)d_in[12];
    const float* ca_b2   = (const float*)d_in[13];
    const float* fc_w    = (const float*)d_in[14];
    const float* fc_b    = (const float*)d_in[15];
    const float* k1_w    = (const float*)d_in[16];
    const float* k1_b    = (const float*)d_in[17];
    const float* k2_w    = (const float*)d_in[18];
    const float* k2_b    = (const float*)d_in[19];
    const float* k3_w    = (const float*)d_in[20];
    const float* k3_b    = (const float*)d_in[21];
    const float* hc_bias = (const float*)d_in[22];
    float* out = (float*)d_out;

    __nv_bfloat16 *padx = nullptr, *pad1 = nullptr, *rcl = nullptr;
    uint32_t* wfr = nullptr;
    cudaGetSymbolAddress((void**)&padx, g_padx);
    cudaGetSymbolAddress((void**)&pad1, g_pad1);
    cudaGetSymbolAddress((void**)&rcl,  g_rcl);
    cudaGetSymbolAddress((void**)&wfr,  g_Wfrag);

    static bool attr_set = false;
    if (!attr_set) {
        cudaFuncSetAttribute(conv_frag_kernel<false>,
                             cudaFuncAttributeMaxDynamicSharedMemorySize, STRIP_B);
        cudaFuncSetAttribute(conv_frag_kernel<true>,
                             cudaFuncAttributeMaxDynamicSharedMemorySize, STRIP_B);
        cudaFuncSetAttribute(final_kernel,
                             cudaFuncAttributeMaxDynamicSharedMemorySize, FIN_SMEM);
        attr_set = true;
    }

    init_kernel<<<2, 256>>>();
    wfrag_kernel<<<288, 256>>>(conv1_w, conv2_w);
    pad_input_kernel<<<dim3(256, NB), 256>>>(x);
    border_cols_kernel<<<dim3(NB, 32), 256>>>(padx);
    border_rows_kernel<<<dim3(NB, 33), 256>>>(padx);

    dim3 cgrid(2, 256, NB);
    conv_frag_kernel<false><<<cgrid, 256, STRIP_B>>>(padx, wfr, conv1_b, prelu_a, pad1);
    border_cols_kernel<<<dim3(NB, 32), 256>>>(pad1);
    border_rows_kernel<<<dim3(NB, 33), 256>>>(pad1);
    conv_frag_kernel<true ><<<cgrid, 256, STRIP_B>>>(pad1, wfr + 36864, conv2_b, prelu_a, rcl);

    sa_kernel<<<dim3(HWN / 256, NB), 256>>>(sa_w, sa_b);

    small_kernel<<<NB, 256>>>(h, ca_w1, ca_b1, ca_a, ca_w2, ca_b2,
                              fc_w, fc_b, k1_w, k1_b, k2_w, k2_b, k3_w, k3_b);

    final_kernel<<<dim3(HWN / 128, NB), 256, FIN_SMEM>>>(hc_bias, x, out);
}

// round 9
// speedup vs baseline: 2.2227x; 1.0861x over previous
#include <cuda_runtime.h>
#include <cuda_bf16.h>
#include <math.h>
#include <float.h>
#include <stdint.h>

#define CH    64
#define IMG_W 256
#define IMG_H 256
#define HWN   65536
#define NB    8
#define PADW  258

// ---------------- device-global scratch -------------------------------------
__device__ __align__(16) __nv_bfloat16 g_padx[NB * PADW * PADW * 128];
__device__ __align__(16) __nv_bfloat16 g_pad1[NB * PADW * PADW * 128];
__device__ __align__(16) __nv_bfloat16 g_rcl [NB * HWN * 128];
__device__ __align__(16) float g_avg[NB * HWN];
__device__ __align__(16) float g_max[NB * HWN];
__device__ __align__(16) float g_sg [NB * HWN];
__device__ float g_chansum[NB * CH];
__device__ __align__(16) __nv_bfloat16 g_Kpk[NB * 2 * 64 * 128];
__device__ __align__(16) uint32_t g_Wfrag[73728];   // [cv][t][wn][sb][ks][h][lane][e]

// ---------------- helpers ----------------------------------------------------
__device__ __forceinline__ int reflect(int v, int n) {
    if (v < 0) v = -v;
    if (v >= n) v = 2 * n - 2 - v;
    return v;
}
__device__ __forceinline__ uint32_t s2u(const void* p) {
    return (uint32_t)__cvta_generic_to_shared(p);
}
__device__ __forceinline__ uint32_t pack2bf(float a, float b) {
    return ((uint32_t)__bfloat16_as_ushort(__float2bfloat16(a))) |
           ((uint32_t)__bfloat16_as_ushort(__float2bfloat16(b)) << 16);
}
__device__ __forceinline__ void ldsm_x4(uint32_t addr, uint32_t& r0, uint32_t& r1,
                                        uint32_t& r2, uint32_t& r3) {
    asm volatile("ldmatrix.sync.aligned.m8n8.x4.shared.b16 {%0,%1,%2,%3}, [%4];"
                 : "=r"(r0), "=r"(r1), "=r"(r2), "=r"(r3) : "r"(addr));
}
__device__ __forceinline__ void mma16816(float* c, const uint32_t* a,
                                         uint32_t b0, uint32_t b1) {
    asm volatile("mma.sync.aligned.m16n8k16.row.col.f32.bf16.bf16.f32 "
                 "{%0,%1,%2,%3}, {%4,%5,%6,%7}, {%8,%9}, {%0,%1,%2,%3};"
                 : "+f"(c[0]), "+f"(c[1]), "+f"(c[2]), "+f"(c[3])
                 : "r"(a[0]), "r"(a[1]), "r"(a[2]), "r"(a[3]), "r"(b0), "r"(b1));
}
__device__ __forceinline__ void cp16(uint32_t dst, const void* src) {
    asm volatile("cp.async.ca.shared.global [%0], [%1], 16;" :: "r"(dst), "l"(src));
}
#define CP_COMMIT() asm volatile("cp.async.commit_group;" ::: "memory")
#define CP_WAIT0()  asm volatile("cp.async.wait_group 0;" ::: "memory")

// ---------------- init ----------------
__global__ void init_kernel() {
    int i = blockIdx.x * blockDim.x + threadIdx.x;
    if (i < NB * CH) g_chansum[i] = 0.0f;
}

// ---------------- weight frag prepack (lane-fastest, coalesced) --------------
__global__ __launch_bounds__(256)
void wfrag_kernel(const float* __restrict__ w1, const float* __restrict__ w2) {
    int idx = blockIdx.x * 256 + threadIdx.x;
    if (idx >= 73728) return;
    int e    = idx & 3;
    int lane = (idx >> 2) & 31;
    int h    = (idx >> 7) & 1;
    int ks   = (idx >> 8) & 3;
    int sb   = (idx >> 10) & 1;
    int wn   = (idx >> 11) & 1;
    int rest = idx >> 12;
    int t    = rest % 9;
    int cv   = rest / 9;
    int nt = 2 * h + (e >> 1);
    int rr = e & 1;
    int n  = wn * 32 + nt * 8 + (lane >> 2);
    int k0 = ks * 16 + rr * 8 + (lane & 3) * 2;
    const float* w = cv ? w2 : w1;
    uint32_t out = 0;
#pragma unroll
    for (int q = 0; q < 2; q++) {
        int ch = k0 + q;
        float v = w[n * 576 + ch * 9 + t];
        __nv_bfloat16 hi = __float2bfloat16(v);
        __nv_bfloat16 bf = sb ? __float2bfloat16(v - __bfloat162float(hi)) : hi;
        out |= ((uint32_t)__bfloat16_as_ushort(bf)) << (16 * q);
    }
    g_Wfrag[idx] = out;
}

// ---------------- record store with reflect mirrors --------------------------
__device__ __forceinline__ void store_rec_mirror(uint4* base, int row0, int col0,
                                                 int row1, int col1,
                                                 const uint4* rec) {
    // row1/col1 < 0 means no mirror
    int rows[2] = { row0, row1 };
    int cols[2] = { col0, col1 };
    int nr = (row1 >= 0) ? 2 : 1;
    int nc = (col1 >= 0) ? 2 : 1;
    for (int r = 0; r < nr; r++)
        for (int c = 0; c < nc; c++) {
            uint4* d = base + ((size_t)rows[r] * PADW + cols[c]) * 16;
#pragma unroll
            for (int j = 0; j < 16; j++) d[j] = rec[j];
        }
}

// ---------------- input prepass: fp32 NCHW -> padded ch-last bf16 hi/lo ------
__global__ __launch_bounds__(256)
void pad_input_kernel(const float* __restrict__ x) {
    const int y = blockIdx.x, b = blockIdx.y, px = threadIdx.x;
    float v[64];
#pragma unroll
    for (int c = 0; c < 64; c++)
        v[c] = x[(((size_t)(b * 64 + c)) << 16) + y * 256 + px];
    uint4 rec[16];
#pragma unroll
    for (int j = 0; j < 16; j++) {
        int k0 = (j & 7) * 8;
        bool lo = j >= 8;
        uint32_t* wp = (uint32_t*)&rec[j];
#pragma unroll
        for (int q = 0; q < 4; q++) {
            float f0 = v[k0 + 2 * q], f1 = v[k0 + 2 * q + 1];
            if (lo) {
                f0 -= __bfloat162float(__float2bfloat16(f0));
                f1 -= __bfloat162float(__float2bfloat16(f1));
            }
            wp[q] = pack2bf(f0, f1);
        }
    }
    uint4* base = (uint4*)(g_padx + (size_t)b * PADW * PADW * 128);
    int rmir = (y == 1) ? 0 : (y == 254 ? 257 : -1);
    int cmir = (px == 1) ? 0 : (px == 254 ? 257 : -1);
    store_rec_mirror(base, y + 1, px + 1, rmir, cmir, rec);
}

// ---------------- conv: mma.sync + frag-LDG weights, M=256/CTA ---------------
#define STRIP_B 66048     // 258 records x 256B (== st: 64*258*4)

template <bool IS_CONV2>
__global__ __launch_bounds__(256, 2)
void conv_frag_kernel(const __nv_bfloat16* __restrict__ pad,
                      const uint32_t* __restrict__ wfrag,
                      const float* __restrict__ bias,
                      const float* __restrict__ prelu_a,
                      __nv_bfloat16* __restrict__ outp)
{
    extern __shared__ char smem[];
    float* st = (float*)smem;
    __shared__ float s_b[64], s_a[64];

    const int tid = threadIdx.x, lane = tid & 31, wid = tid >> 5;
    const int wm = wid & 3, wn = wid >> 2;
    const int y0 = blockIdx.x, b = blockIdx.y;
    const uint32_t su = s2u(smem);

    if (tid < 64) { s_b[tid] = bias[tid]; s_a[tid] = IS_CONV2 ? 0.f : prelu_a[tid]; }

    float acc[4][4][4];
#pragma unroll
    for (int f = 0; f < 4; f++)
#pragma unroll
        for (int g = 0; g < 4; g++)
#pragma unroll
            for (int c = 0; c < 4; c++) acc[f][g][c] = 0.0f;

    const int mrow = wm * 64 + (lane & 15);
    const int asel = lane >> 4;
    const uint4* wf4 = (const uint4*)wfrag;

#pragma unroll
    for (int ky = 0; ky < 3; ky++) {
        __syncthreads();
        {
            const char* src = (const char*)(pad +
                (((size_t)b * PADW + (y0 + ky)) * PADW) * 128);
            for (int i = tid; i < 4128; i += 256) {
                int p = i >> 4, j = i & 15;
                cp16(su + p * 256 + ((j ^ (p & 7)) << 4), src + (size_t)i * 16);
            }
            CP_COMMIT(); CP_WAIT0();
        }
        __syncthreads();
#pragma unroll
        for (int kx = 0; kx < 3; kx++) {
            const uint4* wb = wf4 + ((size_t)((ky * 3 + kx) * 2 + wn) * 16) * 32 + lane;
#pragma unroll
            for (int ks = 0; ks < 4; ks++) {
                uint32_t ah[4][4], al[4][4];
#pragma unroll
                for (int f = 0; f < 4; f++) {
                    int row = kx + mrow + f * 16;
                    uint32_t base = su + row * 256;
                    int chi = ks * 2 + asel;
                    ldsm_x4(base + (((chi    ) ^ (row & 7)) << 4),
                            ah[f][0], ah[f][1], ah[f][2], ah[f][3]);
                    ldsm_x4(base + (((chi + 8) ^ (row & 7)) << 4),
                            al[f][0], al[f][1], al[f][2], al[f][3]);
                }
#pragma unroll
                for (int h = 0; h < 2; h++) {
                    uint4 BH = wb[((0 * 4 + ks) * 2 + h) * 32];
                    uint4 BL = wb[((1 * 4 + ks) * 2 + h) * 32];
                    uint32_t bh[4] = { BH.x, BH.y, BH.z, BH.w };
                    uint32_t bl[4] = { BL.x, BL.y, BL.z, BL.w };
#pragma unroll
                    for (int gg = 0; gg < 2; gg++) {
                        int g = 2 * h + gg;
#pragma unroll
                        for (int f = 0; f < 4; f++) {
                            mma16816(acc[f][g], ah[f], bh[2 * gg], bh[2 * gg + 1]);
                            mma16816(acc[f][g], al[f], bh[2 * gg], bh[2 * gg + 1]);
                            mma16816(acc[f][g], ah[f], bl[2 * gg], bl[2 * gg + 1]);
                        }
                    }
                }
            }
        }
    }

    // ---- epilogue: transpose via st, emit ch-last records ----
    __syncthreads();
#pragma unroll
    for (int f = 0; f < 4; f++)
#pragma unroll
        for (int g = 0; g < 4; g++)
#pragma unroll
            for (int c = 0; c < 4; c++) {
                int m = wm * 64 + f * 16 + (lane >> 2) + ((c >> 1) << 3);
                int n = wn * 32 + g * 8 + ((lane & 3) << 1) + (c & 1);
                st[n * 258 + m] = acc[f][g][c] + s_b[n];
            }
    __syncthreads();

    {
        float v[64];
#pragma unroll
        for (int c = 0; c < 64; c++) v[c] = st[c * 258 + tid];

        if (!IS_CONV2) {
#pragma unroll
            for (int c = 0; c < 64; c++) v[c] = v[c] > 0.f ? v[c] : s_a[c] * v[c];
        } else {
            float sum = 0.f, mx = -FLT_MAX;
#pragma unroll
            for (int c = 0; c < 64; c++) { sum += v[c]; mx = fmaxf(mx, v[c]); }
            const int gp = y0 * 256 + tid;
            g_avg[b * HWN + gp] = sum * (1.0f / CH);
            g_max[b * HWN + gp] = mx;
        }

        uint4 rec[16];
#pragma unroll
        for (int j = 0; j < 16; j++) {
            int k0 = (j & 7) * 8;
            bool lo = j >= 8;
            uint32_t* wp = (uint32_t*)&rec[j];
#pragma unroll
            for (int q = 0; q < 4; q++) {
                float f0 = v[k0 + 2 * q], f1 = v[k0 + 2 * q + 1];
                if (lo) {
                    f0 -= __bfloat162float(__float2bfloat16(f0));
                    f1 -= __bfloat162float(__float2bfloat16(f1));
                }
                wp[q] = pack2bf(f0, f1);
            }
        }

        if (!IS_CONV2) {
            uint4* base = (uint4*)(outp + (size_t)b * PADW * PADW * 128);
            int rmir = (y0 == 1) ? 0 : (y0 == 254 ? 257 : -1);
            int cmir = (tid == 1) ? 0 : (tid == 254 ? 257 : -1);
            store_rec_mirror(base, y0 + 1, tid + 1, rmir, cmir, rec);
        } else {
            uint4* dst = (uint4*)(outp + (((size_t)b << 16) + y0 * 256 + tid) * 128);
#pragma unroll
            for (int j = 0; j < 16; j++) dst[j] = rec[j];
        }
    }

    if (IS_CONV2 && tid < 64) {
        float s = 0.0f;
#pragma unroll 8
        for (int p = 0; p < 256; p++) s += st[tid * 258 + p];
        atomicAdd(&g_chansum[b * CH + tid], s);
    }
}

// ---------------- spatial attention conv -------------------------------------
__global__ __launch_bounds__(256)
void sa_kernel(const float* __restrict__ sa_w, const float* __restrict__ sa_b)
{
    int p = blockIdx.x * 256 + threadIdx.x;
    int b = blockIdx.y;
    int x = p & (IMG_W - 1);
    int y = p >> 8;
    float s = sa_b[0];
#pragma unroll
    for (int ky = 0; ky < 3; ky++) {
        int gy = reflect(y + ky - 1, IMG_H);
#pragma unroll
        for (int kx = 0; kx < 3; kx++) {
            int gx = reflect(x + kx - 1, IMG_W);
            int q = b * HWN + gy * IMG_W + gx;
            s = fmaf(sa_w[ky * 3 + kx],     g_avg[q], s);
            s = fmaf(sa_w[9 + ky * 3 + kx], g_max[q], s);
        }
    }
    g_sg[b * HWN + p] = 1.0f / (1.0f + expf(-s));
}

// ---------------- per-batch small dense math + K prepack ---------------------
__global__ __launch_bounds__(256)
void small_kernel(const float* __restrict__ h_in,
                  const float* __restrict__ ca_w1, const float* __restrict__ ca_b1,
                  const float* __restrict__ ca_a,
                  const float* __restrict__ ca_w2, const float* __restrict__ ca_b2,
                  const float* __restrict__ fc_w,  const float* __restrict__ fc_b,
                  const float* __restrict__ k1_w,  const float* __restrict__ k1_b,
                  const float* __restrict__ k2_w,  const float* __restrict__ k2_b,
                  const float* __restrict__ k3_w,  const float* __restrict__ k3_b)
{
    __shared__ float g[64], t1[32], cv[64], hv[16], t0[16], ta[32], tb[32];
    const int b = blockIdx.x;
    const int tid = threadIdx.x;

    if (tid < 64) g[tid] = g_chansum[b * CH + tid] * (1.0f / HWN);
    if (tid < 16) hv[tid] = h_in[b * 16 + tid];
    __syncthreads();

    if (tid < 32) {
        float s = ca_b1[tid];
        for (int c = 0; c < 64; c++) s = fmaf(ca_w1[tid * 64 + c], g[c], s);
        t1[tid] = s > 0.0f ? s : ca_a[tid] * s;
    }
    if (tid >= 32 && tid < 48) {
        int j = tid - 32;
        float s = fc_b[j];
        for (int c = 0; c < 16; c++) s = fmaf(fc_w[j * 16 + c], hv[c], s);
        t0[j] = s >= 0.0f ? s : 0.01f * s;
    }
    __syncthreads();

    if (tid < 64) {
        float s = ca_b2[tid];
        for (int j = 0; j < 32; j++) s = fmaf(ca_w2[tid * 32 + j], t1[j], s);
        cv[tid] = 1.0f / (1.0f + expf(-s));
    }
    if (tid >= 64 && tid < 96) {
        int j = tid - 64;
        float s = k1_b[j];
        for (int c = 0; c < 16; c++) s = fmaf(k1_w[j * 16 + c], t0[c], s);
        ta[j] = s >= 0.0f ? s : 0.01f * s;
    }
    __syncthreads();

    if (tid < 32) {
        float s = k2_b[tid];
        for (int j = 0; j < 32; j++) s = fmaf(k2_w[tid * 32 + j], ta[j], s);
        tb[tid] = s >= 0.0f ? s : 0.01f * s;
    }
    __syncthreads();

    for (int idx = tid; idx < 8192; idx += 256) {
        float s = k3_b[idx];
        for (int j = 0; j < 32; j++) s = fmaf(k3_w[idx * 32 + j], tb[j], s);
        int o = idx >> 7, i = idx & 127;
        int which = (i >= 64);
        int ch = i & 63;
        float val = which ? s * cv[ch] : s;
        __nv_bfloat16 hi = __float2bfloat16(val);
        __nv_bfloat16 lo = __float2bfloat16(val - __bfloat162float(hi));
        size_t base = (size_t)b * 16384 + (which * 64 + o) * 128 + ch;
        g_Kpk[base]      = hi;
        g_Kpk[base + 64] = lo;
    }
}

// ---------------- final: tensor-core dual matvec + residual ------------------
__device__ __forceinline__ void mma16816v(float* c, uint32_t a0, uint32_t a1,
                                          uint32_t a2, uint32_t a3,
                                          uint32_t b0, uint32_t b1) {
    asm volatile("mma.sync.aligned.m16n8k16.row.col.f32.bf16.bf16.f32 "
                 "{%0,%1,%2,%3}, {%4,%5,%6,%7}, {%8,%9}, {%0,%1,%2,%3};"
                 : "+f"(c[0]), "+f"(c[1]), "+f"(c[2]), "+f"(c[3])
                 : "r"(a0), "r"(a1), "r"(a2), "r"(a3), "r"(b0), "r"(b1));
}

#define PF  136
#define STP 132
#define KM_B   34816
#define SLR_B  32768
#define FIN_SMEM (KM_B + SLR_B + 512)   // 68096

__global__ __launch_bounds__(256)
void final_kernel(const float* __restrict__ hc_bias,
                  const float* __restrict__ x,
                  float* __restrict__ out)
{
    extern __shared__ char smem[];
    __nv_bfloat16* sKm = (__nv_bfloat16*)smem;       // [128 rows][PF]
    char* slabR = smem + KM_B;                       // 128 records x 256B, swizzled
    float* ssg = (float*)(smem + KM_B + SLR_B);      // [128]
    float* st  = (float*)smem;                       // epilogue reuse
    __shared__ float sbias[64];

    const int tid  = threadIdx.x;
    const int lane = tid & 31;
    const int wid  = tid >> 5;
    const int wm   = wid & 3;
    const int wn   = wid >> 2;
    const int b    = blockIdx.y;
    const int p0   = blockIdx.x * 128;
    const uint32_t sr_u = s2u(slabR);

    if (tid < 64) sbias[tid] = hc_bias[tid];
    const __nv_bfloat16* ksrc = g_Kpk + (size_t)b * 16384;
    for (int idx = tid; idx < 2048; idx += 256) {
        int r = idx >> 4, v = (idx & 15) << 3;
        *(uint4*)(sKm + r * PF + v) = *(const uint4*)(ksrc + r * 128 + v);
    }
    {
        const char* src = (const char*)(g_rcl + (((size_t)b << 16) + p0) * 128);
        for (int i = tid; i < 2048; i += 256) {
            int p = i >> 4, j = i & 15;
            cp16(sr_u + p * 256 + ((j ^ (p & 7)) << 4), src + (size_t)i * 16);
        }
        CP_COMMIT();
    }
    if (tid < 128) ssg[tid] = g_sg[b * HWN + p0 + tid];
    CP_WAIT0();
    __syncthreads();

    const uint32_t km_u = s2u(sKm);
    const int mrow = wm * 32 + (lane & 15);
    const int asel = lane >> 4;
    const int bg    = lane >> 4;
    const int bk    = ((lane >> 3) & 1) << 3;
    const int blrow = lane & 7;

    float acc[2][2][4][4];
#pragma unroll
    for (int s = 0; s < 2; s++)
#pragma unroll
        for (int f = 0; f < 2; f++)
#pragma unroll
            for (int g = 0; g < 4; g++)
#pragma unroll
                for (int c = 0; c < 4; c++) acc[s][f][g][c] = 0.0f;

#pragma unroll
    for (int ks = 0; ks < 4; ks++) {
        uint32_t ah[2][4], al[2][4];
#pragma unroll
        for (int f = 0; f < 2; f++) {
            int row = mrow + f * 16;
            uint32_t base = sr_u + row * 256;
            int chi = ks * 2 + asel;
            ldsm_x4(base + (((chi    ) ^ (row & 7)) << 4),
                    ah[f][0], ah[f][1], ah[f][2], ah[f][3]);
            ldsm_x4(base + (((chi + 8) ^ (row & 7)) << 4),
                    al[f][0], al[f][1], al[f][2], al[f][3]);
        }
#pragma unroll
        for (int s = 0; s < 2; s++) {
#pragma unroll
            for (int gp = 0; gp < 2; gp++) {
                int brow = s * 64 + wn * 32 + (2 * gp + bg) * 8 + blrow;
                uint32_t bb = km_u + (uint32_t)((brow * PF + bk + ks * 16) * 2);
                uint32_t bh0, bh1, bh2, bh3, bl0, bl1, bl2, bl3;
                ldsm_x4(bb,       bh0, bh1, bh2, bh3);
                ldsm_x4(bb + 128, bl0, bl1, bl2, bl3);
#pragma unroll
                for (int f = 0; f < 2; f++) {
                    mma16816(acc[s][f][2 * gp],     ah[f], bh0, bh1);
                    mma16816(acc[s][f][2 * gp],     al[f], bh0, bh1);
                    mma16816(acc[s][f][2 * gp],     ah[f], bl0, bl1);
                    mma16816(acc[s][f][2 * gp + 1], ah[f], bh2, bh3);
                    mma16816(acc[s][f][2 * gp + 1], al[f], bh2, bh3);
                    mma16816(acc[s][f][2 * gp + 1], ah[f], bl2, bl3);
                }
            }
        }
    }

    __syncthreads();
#pragma unroll
    for (int f = 0; f < 2; f++)
#pragma unroll
        for (int g = 0; g < 4; g++)
#pragma unroll
            for (int c = 0; c < 4; c++) {
                int m = wm * 32 + f * 16 + (lane >> 2) + ((c >> 1) << 3);
                int n = wn * 32 + g * 8 + ((lane & 3) << 1) + (c & 1);
                st[n * STP + m] = ssg[m] * acc[0][f][g][c] + acc[1][f][g][c] + sbias[n];
            }
    __syncthreads();

    const size_t obase = (size_t)b * CH * HWN + p0;
    for (int idx = tid; idx < 2048; idx += 256) {
        int oc = idx >> 5, v = (idx & 31) << 2;
        size_t gi = obase + (size_t)oc * HWN + v;
        float4 xv = *(const float4*)&x[gi];
        float4 sv = *(const float4*)&st[oc * STP + v];
        float4 ov = { xv.x + sv.x, xv.y + sv.y, xv.z + sv.z, xv.w + sv.w };
        *(float4*)&out[gi] = ov;
    }
}

// ---------------- launch ----------------------------------------------------
extern "C" void kernel_launch(void* const* d_in, const int* in_sizes, int n_in,
                              void* d_out, int out_size)
{
    const float* x       = (const float*)d_in[0];
    const float* h       = (const float*)d_in[1];
    const float* conv1_w = (const float*)d_in[2];
    const float* conv1_b = (const float*)d_in[3];
    const float* prelu_a = (const float*)d_in[4];
    const float* conv2_w = (const float*)d_in[5];
    const float* conv2_b = (const float*)d_in[6];
    const float* sa_w    = (const float*)d_in[7];
    const float* sa_b    = (const float*)d_in[8];
    const float* ca_w1   = (const float*)d_in[9];
    const float* ca_b1   = (const float*)d_in[10];
    const float* ca_a    = (const float*)d_in[11];
    const float* ca_w2   = (const float*)d_in[12];
    const float* ca_b2   = (const float*)d_in[13];
    const float* fc_w    = (const float*)d_in[14];
    const float* fc_b    = (const float*)d_in[15];
    const float* k1_w    = (const float*)d_in[16];
    const float* k1_b    = (const float*)d_in[17];
    const float* k2_w    = (const float*)d_in[18];
    const float* k2_b    = (const float*)d_in[19];
    const float* k3_w    = (const float*)d_in[20];
    const float* k3_b    = (const float*)d_in[21];
    const float* hc_bias = (const float*)d_in[22];
    float* out = (float*)d_out;

    __nv_bfloat16 *padx = nullptr, *pad1 = nullptr, *rcl = nullptr;
    uint32_t* wfr = nullptr;
    cudaGetSymbolAddress((void**)&padx, g_padx);
    cudaGetSymbolAddress((void**)&pad1, g_pad1);
    cudaGetSymbolAddress((void**)&rcl,  g_rcl);
    cudaGetSymbolAddress((void**)&wfr,  g_Wfrag);

    static bool attr_set = false;
    if (!attr_set) {
        cudaFuncSetAttribute(conv_frag_kernel<false>,
                             cudaFuncAttributeMaxDynamicSharedMemorySize, STRIP_B);
        cudaFuncSetAttribute(conv_frag_kernel<true>,
                             cudaFuncAttributeMaxDynamicSharedMemorySize, STRIP_B);
        cudaFuncSetAttribute(final_kernel,
                             cudaFuncAttributeMaxDynamicSharedMemorySize, FIN_SMEM);
        attr_set = true;
    }

    init_kernel<<<2, 256>>>();
    wfrag_kernel<<<288, 256>>>(conv1_w, conv2_w);
    pad_input_kernel<<<dim3(256, NB), 256>>>(x);

    dim3 cgrid(IMG_H, NB);
    conv_frag_kernel<false><<<cgrid, 256, STRIP_B>>>(padx, wfr, conv1_b, prelu_a, pad1);
    conv_frag_kernel<true ><<<cgrid, 256, STRIP_B>>>(pad1, wfr + 36864, conv2_b, prelu_a, rcl);

    sa_kernel<<<dim3(HWN / 256, NB), 256>>>(sa_w, sa_b);

    small_kernel<<<NB, 256>>>(h, ca_w1, ca_b1, ca_a, ca_w2, ca_b2,
                              fc_w, fc_b, k1_w, k1_b, k2_w, k2_b, k3_w, k3_b);

    final_kernel<<<dim3(HWN / 128, NB), 256, FIN_SMEM>>>(hc_bias, x, out);
}